// round 13
// baseline (speedup 1.0000x reference)
#include <cuda_runtime.h>
#include <cuda_bf16.h>
#include <cstdint>

#define BATCH  2
#define SLEN   2048
#define DMODEL 1024
#define NHEAD  16
#define DKH    64
#define MROWS  (BATCH * SLEN)   // 4096

// ---------------- scratch (allocation-free rule: __device__ globals) --------
__device__ __align__(16) __nv_bfloat16 g_xhi[MROWS * DMODEL];
__device__ __align__(16) __nv_bfloat16 g_xlo[MROWS * DMODEL];
__device__ __align__(16) __nv_bfloat16 g_qhi[MROWS * DMODEL];
__device__ __align__(16) __nv_bfloat16 g_qlo[MROWS * DMODEL];
__device__ __align__(16) __nv_bfloat16 g_khi[MROWS * DMODEL];
__device__ __align__(16) __nv_bfloat16 g_klo[MROWS * DMODEL];
__device__ __align__(16) __nv_bfloat16 g_vhi[MROWS * DMODEL];
__device__ __align__(16) __nv_bfloat16 g_vlo[MROWS * DMODEL];
__device__ __align__(16) __nv_bfloat16 g_ahi[MROWS * DMODEL];
__device__ __align__(16) __nv_bfloat16 g_alo[MROWS * DMODEL];
__device__ __align__(16) __nv_bfloat16 g_wh[4][DMODEL * DMODEL];
__device__ __align__(16) __nv_bfloat16 g_wl[4][DMODEL * DMODEL];
__device__ __align__(16) __nv_bfloat16 g_bias[(size_t)BATCH * SLEN * SLEN];

// ---------------- helpers ----------------------------------------------------
__device__ __forceinline__ uint32_t smem_u32(const void* p) {
    return (uint32_t)__cvta_generic_to_shared(p);
}
__device__ __forceinline__ void ldsm_x4(uint32_t (&r)[4], uint32_t addr) {
    asm volatile("ldmatrix.sync.aligned.m8n8.x4.shared.b16 {%0,%1,%2,%3}, [%4];"
                 : "=r"(r[0]), "=r"(r[1]), "=r"(r[2]), "=r"(r[3]) : "r"(addr));
}
__device__ __forceinline__ void ldsm_x4_t(uint32_t (&r)[4], uint32_t addr) {
    asm volatile("ldmatrix.sync.aligned.m8n8.x4.trans.shared.b16 {%0,%1,%2,%3}, [%4];"
                 : "=r"(r[0]), "=r"(r[1]), "=r"(r[2]), "=r"(r[3]) : "r"(addr));
}
__device__ __forceinline__ void mma_bf16(float (&d)[4], const uint32_t (&a)[4],
                                         uint32_t b0, uint32_t b1) {
    asm volatile("mma.sync.aligned.m16n8k16.row.col.f32.bf16.bf16.f32 "
                 "{%0,%1,%2,%3}, {%4,%5,%6,%7}, {%8,%9}, {%0,%1,%2,%3};"
                 : "+f"(d[0]), "+f"(d[1]), "+f"(d[2]), "+f"(d[3])
                 : "r"(a[0]), "r"(a[1]), "r"(a[2]), "r"(a[3]), "r"(b0), "r"(b1));
}
__device__ __forceinline__ float ex2(float x) {
    float y;
    asm("ex2.approx.ftz.f32 %0, %1;" : "=f"(y) : "f"(x));
    return y;
}
__device__ __forceinline__ uint32_t pack_hi(float f0, float f1, __nv_bfloat162& h2) {
    h2 = __floats2bfloat162_rn(f0, f1);
    return *(uint32_t*)&h2;
}
__device__ __forceinline__ uint32_t pack_lo(float f0, float f1, const __nv_bfloat162& h2) {
    __nv_bfloat162 l2 = __floats2bfloat162_rn(f0 - __bfloat162float(h2.x),
                                              f1 - __bfloat162float(h2.y));
    return *(uint32_t*)&l2;
}

// ---------------- fp32 -> (hi, lo) bf16 split --------------------------------
__global__ __launch_bounds__(256) void split_f32(
    const float4* __restrict__ x, __nv_bfloat162* __restrict__ hi,
    __nv_bfloat162* __restrict__ lo, int n4)
{
    int i = blockIdx.x * blockDim.x + threadIdx.x;
    if (i >= n4) return;
    float4 v = x[i];
    __nv_bfloat162 h0, h1;
    uint32_t u0 = pack_hi(v.x, v.y, h0), u1 = pack_hi(v.z, v.w, h1);
    uint32_t l0 = pack_lo(v.x, v.y, h0), l1 = pack_lo(v.z, v.w, h1);
    *(uint32_t*)&hi[2 * i] = u0; *(uint32_t*)&hi[2 * i + 1] = u1;
    *(uint32_t*)&lo[2 * i] = l0; *(uint32_t*)&lo[2 * i + 1] = l1;
}

// ---------------- mask (int) -> additive bf16 bias ---------------------------
__global__ __launch_bounds__(256) void mask_to_bias(
    const int4* __restrict__ mk, __nv_bfloat162* __restrict__ out, int n4)
{
    int i = blockIdx.x * blockDim.x + threadIdx.x;
    if (i >= n4) return;
    int4 m = mk[i];
    out[2 * i]     = __floats2bfloat162_rn(m.x ? 0.f : -1e9f, m.y ? 0.f : -1e9f);
    out[2 * i + 1] = __floats2bfloat162_rn(m.z ? 0.f : -1e9f, m.w ? 0.f : -1e9f);
}

// ---------------- mma.sync GEMM: 256x128 CTA tile, single wave ---------------
// 512 threads, 4x4 warp grid, warp tile 64x32. K-chunk 64, double-buffered.
#define KCH      64
#define NCHUNK   (DMODEL / KCH)
#define A_TILE_B 32768            // 256 rows x 128B
#define W_TILE_B 16384            // 128 rows x 128B
#define STAGE_B  (2 * A_TILE_B + 2 * W_TILE_B)   // 98304
#define GEMM_SMEM (2 * STAGE_B)                  // 196608

__global__ __launch_bounds__(512, 1) void gemm_mma(
    const __nv_bfloat16* __restrict__ xhi, const __nv_bfloat16* __restrict__ xlo,
    const __nv_bfloat16* __restrict__ whi, const __nv_bfloat16* __restrict__ wlo,
    const float* __restrict__ bias, float* __restrict__ C,
    __nv_bfloat16* __restrict__ Chi, __nv_bfloat16* __restrict__ Clo, float scale)
{
    extern __shared__ __align__(1024) char smem[];
    const uint32_t sb = smem_u32(smem);
    const int tid = threadIdx.x, wid = tid >> 5, lane = tid & 31;
    const int warp_m = wid >> 2, warp_n = wid & 3;   // 4 x 4 warps
    const int bn = blockIdx.x * 128, bm = blockIdx.y * 256;

    float acc[4][4][4];
#pragma unroll
    for (int i = 0; i < 4; i++)
#pragma unroll
        for (int j = 0; j < 4; j++)
#pragma unroll
            for (int e = 0; e < 4; e++) acc[i][j][e] = 0.0f;

    const __nv_bfloat16* srcs[4] = {
        xhi + (size_t)bm * DMODEL, xlo + (size_t)bm * DMODEL,
        whi + (size_t)bn * DMODEL, wlo + (size_t)bn * DMODEL };

    auto load_chunk = [&](int chunk, int stage) {
        const int k0 = chunk * KCH;
        const uint32_t st = sb + stage * STAGE_B;
        // 6144 x 16B: iters 0-7 cover A (idx<4096), 8-11 cover W.
#pragma unroll
        for (int i = 0; i < 12; i++) {
            int idx = tid + i * 512;
            uint32_t dst; const void* g;
            if (idx < 4096) {
                int comp = idx >> 11, r = (idx >> 3) & 255, c8 = idx & 7;
                uint32_t boff = r * 128 + c8 * 16;
                uint32_t sw = boff ^ ((boff >> 3) & 0x70);
                dst = st + comp * A_TILE_B + sw;
                g = srcs[comp] + (size_t)r * DMODEL + k0 + c8 * 8;
            } else {
                int idx2 = idx - 4096;
                int comp = idx2 >> 10, r = (idx2 >> 3) & 127, c8 = idx2 & 7;
                uint32_t boff = r * 128 + c8 * 16;
                uint32_t sw = boff ^ ((boff >> 3) & 0x70);
                dst = st + 2 * A_TILE_B + comp * W_TILE_B + sw;
                g = srcs[2 + comp] + (size_t)r * DMODEL + k0 + c8 * 8;
            }
            asm volatile("cp.async.cg.shared.global [%0], [%1], 16;"
                         :: "r"(dst), "l"(g));
        }
        asm volatile("cp.async.commit_group;" ::: "memory");
    };

    load_chunk(0, 0);

    for (int i = 0; i < NCHUNK; i++) {
        if (i + 1 < NCHUNK) {
            load_chunk(i + 1, (i + 1) & 1);
            asm volatile("cp.async.wait_group 1;" ::: "memory");
        } else {
            asm volatile("cp.async.wait_group 0;" ::: "memory");
        }
        __syncthreads();

        const uint32_t st = sb + (i & 1) * STAGE_B;
#pragma unroll
        for (int ks = 0; ks < 4; ks++) {
            const int cb = ks * 32 + ((lane >> 4) << 4);
            uint32_t wh[2][4], wl[2][4];
#pragma unroll
            for (int np = 0; np < 2; np++) {
                int r = warp_n * 32 + np * 16 + (lane & 15);
                uint32_t boff = r * 128 + cb;
                uint32_t sw = boff ^ ((boff >> 3) & 0x70);
                ldsm_x4(wh[np], st + 2 * A_TILE_B + sw);
                ldsm_x4(wl[np], st + 2 * A_TILE_B + W_TILE_B + sw);
            }
#pragma unroll
            for (int mi = 0; mi < 4; mi++) {
                uint32_t ah[4], al[4];
                int r = warp_m * 64 + mi * 16 + (lane & 15);
                uint32_t boff = r * 128 + cb;
                uint32_t sw = boff ^ ((boff >> 3) & 0x70);
                ldsm_x4(ah, st + sw);
                ldsm_x4(al, st + A_TILE_B + sw);
                // term-major within the mi block
#pragma unroll
                for (int nj = 0; nj < 4; nj++) {
                    int np = nj >> 1, o = nj & 1;
                    mma_bf16(acc[mi][nj], ah, wh[np][o], wh[np][o + 2]);
                }
#pragma unroll
                for (int nj = 0; nj < 4; nj++) {
                    int np = nj >> 1, o = nj & 1;
                    mma_bf16(acc[mi][nj], ah, wl[np][o], wl[np][o + 2]);
                }
#pragma unroll
                for (int nj = 0; nj < 4; nj++) {
                    int np = nj >> 1, o = nj & 1;
                    mma_bf16(acc[mi][nj], al, wh[np][o], wh[np][o + 2]);
                }
            }
        }
        __syncthreads();
    }

    const int r0 = lane >> 2, c0 = (lane & 3) * 2;
#pragma unroll
    for (int mi = 0; mi < 4; mi++) {
#pragma unroll
        for (int nj = 0; nj < 4; nj++) {
            int row = bm + warp_m * 64 + mi * 16 + r0;
            int col = bn + warp_n * 32 + nj * 8 + c0;
            float2 b2 = *(const float2*)&bias[col];
            float v0 = (acc[mi][nj][0] + b2.x) * scale;
            float v1 = (acc[mi][nj][1] + b2.y) * scale;
            float v2 = (acc[mi][nj][2] + b2.x) * scale;
            float v3 = (acc[mi][nj][3] + b2.y) * scale;
            if (Chi) {
                __nv_bfloat162 h0, h1;
                uint32_t u0 = pack_hi(v0, v1, h0), u1 = pack_hi(v2, v3, h1);
                uint32_t l0 = pack_lo(v0, v1, h0), l1 = pack_lo(v2, v3, h1);
                *(uint32_t*)&Chi[(size_t)row * DMODEL + col] = u0;
                *(uint32_t*)&Clo[(size_t)row * DMODEL + col] = l0;
                *(uint32_t*)&Chi[(size_t)(row + 8) * DMODEL + col] = u1;
                *(uint32_t*)&Clo[(size_t)(row + 8) * DMODEL + col] = l1;
            } else {
                *(float2*)&C[(size_t)row * DMODEL + col] = make_float2(v0, v1);
                *(float2*)&C[(size_t)(row + 8) * DMODEL + col] = make_float2(v2, v3);
            }
        }
    }
}

// ---------------- flash attention (R12 form) ---------------------------------
#define FA_STAGE 49152
#define FA_SMEM  (2 * FA_STAGE)
#define NBLK     (SLEN / 64)

__global__ __launch_bounds__(256, 1) void flash_attn_mma(
    const __nv_bfloat16* __restrict__ Qhi, const __nv_bfloat16* __restrict__ Qlo,
    const __nv_bfloat16* __restrict__ Khi, const __nv_bfloat16* __restrict__ Klo,
    const __nv_bfloat16* __restrict__ Vhi, const __nv_bfloat16* __restrict__ Vlo,
    const __nv_bfloat16* __restrict__ bias,
    __nv_bfloat16* __restrict__ Ahi, __nv_bfloat16* __restrict__ Alo)
{
    extern __shared__ __align__(1024) char smem[];
    const uint32_t sb = smem_u32(smem);
    const int tid = threadIdx.x, wid = tid >> 5, lane = tid & 31;
    const int q0 = blockIdx.x * 128, h = blockIdx.y, b = blockIdx.z;

    const size_t tok0 = (size_t)b * SLEN;
    const size_t hoff = (size_t)h * DKH;
    const int qr = q0 + wid * 16 + (lane >> 2);

    uint32_t qh[4][4], ql[4][4];
    {
        const size_t b0 = (tok0 + qr) * DMODEL + hoff;
        const size_t b1 = (tok0 + qr + 8) * DMODEL + hoff;
#pragma unroll
        for (int t = 0; t < 4; t++) {
            int c = t * 16 + 2 * (lane & 3);
            qh[t][0] = *(const uint32_t*)&Qhi[b0 + c];
            qh[t][1] = *(const uint32_t*)&Qhi[b1 + c];
            qh[t][2] = *(const uint32_t*)&Qhi[b0 + c + 8];
            qh[t][3] = *(const uint32_t*)&Qhi[b1 + c + 8];
            ql[t][0] = *(const uint32_t*)&Qlo[b0 + c];
            ql[t][1] = *(const uint32_t*)&Qlo[b1 + c];
            ql[t][2] = *(const uint32_t*)&Qlo[b0 + c + 8];
            ql[t][3] = *(const uint32_t*)&Qlo[b1 + c + 8];
        }
    }

    const __nv_bfloat16* srcs[4] = {
        Khi + tok0 * DMODEL + hoff, Klo + tok0 * DMODEL + hoff,
        Vhi + tok0 * DMODEL + hoff, Vlo + tok0 * DMODEL + hoff };
    const __nv_bfloat16* brow = bias + (tok0 + q0) * SLEN;

    auto load_kv = [&](int blk, int stage) {
        const int k0 = blk * 64;
        const uint32_t st = sb + stage * FA_STAGE;
#pragma unroll
        for (int i = 0; i < 8; i++) {
            int idx = tid + i * 256;
            int a = idx >> 9, r = (idx >> 3) & 63, c8 = idx & 7;
            uint32_t boff = r * 128 + c8 * 16;
            uint32_t sw = boff ^ ((boff >> 3) & 0x70);
            const void* g = srcs[a] + (size_t)(k0 + r) * DMODEL + c8 * 8;
            asm volatile("cp.async.cg.shared.global [%0], [%1], 16;"
                         :: "r"(st + a * 8192 + sw), "l"(g));
        }
#pragma unroll
        for (int i = 0; i < 4; i++) {
            int idx = tid + i * 256;
            int r = idx >> 3, c8 = idx & 7;
            uint32_t boff = r * 128 + c8 * 16;
            uint32_t sw = boff ^ ((boff >> 3) & 0x70);
            const void* g = brow + (size_t)r * SLEN + k0 + c8 * 8;
            asm volatile("cp.async.cg.shared.global [%0], [%1], 16;"
                         :: "r"(st + 32768 + sw), "l"(g));
        }
        asm volatile("cp.async.commit_group;" ::: "memory");
    };

    float l[2] = { 0.f, 0.f };
    float o[8][4];
#pragma unroll
    for (int j = 0; j < 8; j++)
#pragma unroll
        for (int e = 0; e < 4; e++) o[j][e] = 0.f;

    load_kv(0, 0);

    for (int blk = 0; blk < NBLK; blk++) {
        if (blk + 1 < NBLK) {
            load_kv(blk + 1, (blk + 1) & 1);
            asm volatile("cp.async.wait_group 1;" ::: "memory");
        } else {
            asm volatile("cp.async.wait_group 0;" ::: "memory");
        }
        __syncthreads();
        const uint32_t st = sb + (blk & 1) * FA_STAGE;

        float S[8][4];
#pragma unroll
        for (int j = 0; j < 8; j++)
#pragma unroll
            for (int e = 0; e < 4; e++) S[j][e] = 0.f;

#pragma unroll
        for (int t = 0; t < 4; t++) {
            const int cb = t * 32 + ((lane >> 4) << 4);
#pragma unroll
            for (int np = 0; np < 4; np++) {
                int r = np * 16 + (lane & 15);
                uint32_t boff = r * 128 + cb;
                uint32_t sw = boff ^ ((boff >> 3) & 0x70);
                uint32_t kh[4], kl[4];
                ldsm_x4(kh, st + sw);
                ldsm_x4(kl, st + 8192 + sw);
#pragma unroll
                for (int o2 = 0; o2 < 2; o2++)
                    mma_bf16(S[np * 2 + o2], qh[t], kh[o2], kh[o2 + 2]);
#pragma unroll
                for (int o2 = 0; o2 < 2; o2++)
                    mma_bf16(S[np * 2 + o2], qh[t], kl[o2], kl[o2 + 2]);
#pragma unroll
                for (int o2 = 0; o2 < 2; o2++)
                    mma_bf16(S[np * 2 + o2], ql[t], kh[o2], kh[o2 + 2]);
            }
        }

#pragma unroll
        for (int j2 = 0; j2 < 4; j2++) {
            uint32_t bf[4];
            int rr = wid * 16 + ((lane >> 3) & 1) * 8 + (lane & 7);
            int cc = (j2 * 2 + (lane >> 4)) * 16;
            uint32_t boff = rr * 128 + cc;
            uint32_t sw = boff ^ ((boff >> 3) & 0x70);
            ldsm_x4(bf, st + 32768 + sw);
            float2 f;
            f = __bfloat1622float2(*(__nv_bfloat162*)&bf[0]);
            S[2 * j2][0] += f.x; S[2 * j2][1] += f.y;
            f = __bfloat1622float2(*(__nv_bfloat162*)&bf[1]);
            S[2 * j2][2] += f.x; S[2 * j2][3] += f.y;
            f = __bfloat1622float2(*(__nv_bfloat162*)&bf[2]);
            S[2 * j2 + 1][0] += f.x; S[2 * j2 + 1][1] += f.y;
            f = __bfloat1622float2(*(__nv_bfloat162*)&bf[3]);
            S[2 * j2 + 1][2] += f.x; S[2 * j2 + 1][3] += f.y;
        }
#pragma unroll
        for (int j = 0; j < 8; j++) {
            S[j][0] = ex2(S[j][0]); S[j][1] = ex2(S[j][1]);
            S[j][2] = ex2(S[j][2]); S[j][3] = ex2(S[j][3]);
            l[0] += S[j][0] + S[j][1];
            l[1] += S[j][2] + S[j][3];
        }

#pragma unroll
        for (int t = 0; t < 4; t++) {
            uint32_t ph[4], pl[4];
            {
                __nv_bfloat162 h2;
                ph[0] = pack_hi(S[2 * t][0], S[2 * t][1], h2);
                pl[0] = pack_lo(S[2 * t][0], S[2 * t][1], h2);
                ph[1] = pack_hi(S[2 * t][2], S[2 * t][3], h2);
                pl[1] = pack_lo(S[2 * t][2], S[2 * t][3], h2);
                ph[2] = pack_hi(S[2 * t + 1][0], S[2 * t + 1][1], h2);
                pl[2] = pack_lo(S[2 * t + 1][0], S[2 * t + 1][1], h2);
                ph[3] = pack_hi(S[2 * t + 1][2], S[2 * t + 1][3], h2);
                pl[3] = pack_lo(S[2 * t + 1][2], S[2 * t + 1][3], h2);
            }
            const int vkey = t * 16 + ((lane >> 3) & 1) * 8 + (lane & 7);
#pragma unroll
            for (int g = 0; g < 4; g++) {
                int dcol = g * 16 + ((lane >> 4) & 1) * 8;
                uint32_t boff = vkey * 128 + dcol * 2;
                uint32_t sw = boff ^ ((boff >> 3) & 0x70);
                uint32_t vh[4], vl[4];
                ldsm_x4_t(vh, st + 16384 + sw);
                ldsm_x4_t(vl, st + 24576 + sw);
#pragma unroll
                for (int o2 = 0; o2 < 2; o2++)
                    mma_bf16(o[g * 2 + o2], ph, vh[o2 * 2], vh[o2 * 2 + 1]);
#pragma unroll
                for (int o2 = 0; o2 < 2; o2++)
                    mma_bf16(o[g * 2 + o2], ph, vl[o2 * 2], vl[o2 * 2 + 1]);
#pragma unroll
                for (int o2 = 0; o2 < 2; o2++)
                    mma_bf16(o[g * 2 + o2], pl, vh[o2 * 2], vh[o2 * 2 + 1]);
            }
        }
        __syncthreads();
    }

    l[0] += __shfl_xor_sync(0xffffffffu, l[0], 1);
    l[0] += __shfl_xor_sync(0xffffffffu, l[0], 2);
    l[1] += __shfl_xor_sync(0xffffffffu, l[1], 1);
    l[1] += __shfl_xor_sync(0xffffffffu, l[1], 2);
    const float i0 = 1.f / l[0], i1 = 1.f / l[1];
#pragma unroll
    for (int j = 0; j < 8; j++) {
        int c = j * 8 + 2 * (lane & 3);
        size_t a0 = (tok0 + qr) * DMODEL + hoff + c;
        size_t a1 = (tok0 + qr + 8) * DMODEL + hoff + c;
        __nv_bfloat162 h2;
        float f0 = o[j][0] * i0, f1 = o[j][1] * i0;
        uint32_t u = pack_hi(f0, f1, h2), v = pack_lo(f0, f1, h2);
        *(uint32_t*)&Ahi[a0] = u; *(uint32_t*)&Alo[a0] = v;
        f0 = o[j][2] * i1; f1 = o[j][3] * i1;
        u = pack_hi(f0, f1, h2); v = pack_lo(f0, f1, h2);
        *(uint32_t*)&Ahi[a1] = u; *(uint32_t*)&Alo[a1] = v;
    }
}

// ---------------- launcher ---------------------------------------------------
extern "C" void kernel_launch(void* const* d_in, const int* in_sizes, int n_in,
                              void* d_out, int out_size)
{
    const float* query = (const float*)d_in[0];
    const float* key   = (const float*)d_in[1];
    const float* value = (const float*)d_in[2];
    const int*   mask  = (const int*)d_in[3];
    const float* Wq    = (const float*)d_in[4];
    const float* bq    = (const float*)d_in[5];
    const float* Wk    = (const float*)d_in[6];
    const float* bk    = (const float*)d_in[7];
    const float* Wv    = (const float*)d_in[8];
    const float* bv    = (const float*)d_in[9];
    const float* Wo    = (const float*)d_in[10];
    const float* bo    = (const float*)d_in[11];
    float* out = (float*)d_out;

    __nv_bfloat16 *xhi, *xlo, *qhi, *qlo, *khi, *klo, *vhi, *vlo, *ahi, *alo, *bb;
    __nv_bfloat16 *wh[4], *wl[4];
    cudaGetSymbolAddress((void**)&xhi, g_xhi);
    cudaGetSymbolAddress((void**)&xlo, g_xlo);
    cudaGetSymbolAddress((void**)&qhi, g_qhi);
    cudaGetSymbolAddress((void**)&qlo, g_qlo);
    cudaGetSymbolAddress((void**)&khi, g_khi);
    cudaGetSymbolAddress((void**)&klo, g_klo);
    cudaGetSymbolAddress((void**)&vhi, g_vhi);
    cudaGetSymbolAddress((void**)&vlo, g_vlo);
    cudaGetSymbolAddress((void**)&ahi, g_ahi);
    cudaGetSymbolAddress((void**)&alo, g_alo);
    cudaGetSymbolAddress((void**)&bb,  g_bias);
    {
        __nv_bfloat16 *p;
        cudaGetSymbolAddress((void**)&p, g_wh);
        for (int i = 0; i < 4; i++) wh[i] = p + (size_t)i * DMODEL * DMODEL;
        cudaGetSymbolAddress((void**)&p, g_wl);
        for (int i = 0; i < 4; i++) wl[i] = p + (size_t)i * DMODEL * DMODEL;
    }

    cudaFuncSetAttribute(gemm_mma, cudaFuncAttributeMaxDynamicSharedMemorySize, GEMM_SMEM);
    cudaFuncSetAttribute(flash_attn_mma, cudaFuncAttributeMaxDynamicSharedMemorySize, FA_SMEM);

    const int nx4 = MROWS * DMODEL / 4;
    const int nw4 = DMODEL * DMODEL / 4;
    const int nb4 = BATCH * SLEN * SLEN / 4;
    dim3 gg(DMODEL / 128, MROWS / 256);   // (8, 16) = 128 CTAs, single wave

    mask_to_bias<<<nb4 / 256, 256>>>((const int4*)mask, (__nv_bfloat162*)bb, nb4);

    const float* Ws[4] = { Wq, Wk, Wv, Wo };
    for (int i = 0; i < 4; i++)
        split_f32<<<nw4 / 256, 256>>>((const float4*)Ws[i], (__nv_bfloat162*)wh[i],
                                      (__nv_bfloat162*)wl[i], nw4);

    const float QSCALE = 0.125f * 1.4426950408889634f;

    split_f32<<<nx4 / 256, 256>>>((const float4*)query, (__nv_bfloat162*)xhi,
                                  (__nv_bfloat162*)xlo, nx4);
    gemm_mma<<<gg, 512, GEMM_SMEM>>>(xhi, xlo, wh[0], wl[0], bq, nullptr, qhi, qlo, QSCALE);

    split_f32<<<nx4 / 256, 256>>>((const float4*)key, (__nv_bfloat162*)xhi,
                                  (__nv_bfloat162*)xlo, nx4);
    gemm_mma<<<gg, 512, GEMM_SMEM>>>(xhi, xlo, wh[1], wl[1], bk, nullptr, khi, klo, 1.f);

    split_f32<<<nx4 / 256, 256>>>((const float4*)value, (__nv_bfloat162*)xhi,
                                  (__nv_bfloat162*)xlo, nx4);
    gemm_mma<<<gg, 512, GEMM_SMEM>>>(xhi, xlo, wh[2], wl[2], bv, nullptr, vhi, vlo, 1.f);

    dim3 fg(SLEN / 128, NHEAD, BATCH);   // (16, 16, 2)
    flash_attn_mma<<<fg, 256, FA_SMEM>>>(qhi, qlo, khi, klo, vhi, vlo, bb, ahi, alo);

    gemm_mma<<<gg, 512, GEMM_SMEM>>>(ahi, alo, wh[3], wl[3], bo, out, nullptr, nullptr, 1.f);
}

// round 14
// speedup vs baseline: 1.0208x; 1.0208x over previous
#include <cuda_runtime.h>
#include <cuda_bf16.h>
#include <cstdint>

#define BATCH  2
#define SLEN   2048
#define DMODEL 1024
#define NHEAD  16
#define DKH    64
#define MROWS  (BATCH * SLEN)   // 4096

#define NX4  (MROWS * DMODEL / 4)        // 1048576  (one input tensor, float4 units)
#define NW4  (DMODEL * DMODEL / 4)       // 262144   (one weight, float4 units)
#define NB4  (BATCH * SLEN * SLEN / 4)   // 2097152  (mask, int4 units)
#define PREP_UNITS (3 * NX4 + 4 * NW4 + NB4)   // 6291456

// ---------------- scratch (allocation-free rule: __device__ globals) --------
__device__ __align__(16) __nv_bfloat16 g_xh[3][MROWS * DMODEL];
__device__ __align__(16) __nv_bfloat16 g_xl[3][MROWS * DMODEL];
__device__ __align__(16) __nv_bfloat16 g_qhi[MROWS * DMODEL];
__device__ __align__(16) __nv_bfloat16 g_qlo[MROWS * DMODEL];
__device__ __align__(16) __nv_bfloat16 g_khi[MROWS * DMODEL];
__device__ __align__(16) __nv_bfloat16 g_klo[MROWS * DMODEL];
__device__ __align__(16) __nv_bfloat16 g_vhi[MROWS * DMODEL];
__device__ __align__(16) __nv_bfloat16 g_vlo[MROWS * DMODEL];
__device__ __align__(16) __nv_bfloat16 g_ahi[MROWS * DMODEL];
__device__ __align__(16) __nv_bfloat16 g_alo[MROWS * DMODEL];
__device__ __align__(16) __nv_bfloat16 g_wh[4][DMODEL * DMODEL];
__device__ __align__(16) __nv_bfloat16 g_wl[4][DMODEL * DMODEL];
__device__ __align__(16) __nv_bfloat16 g_bias[(size_t)BATCH * SLEN * SLEN];

// ---------------- helpers ----------------------------------------------------
__device__ __forceinline__ uint32_t smem_u32(const void* p) {
    return (uint32_t)__cvta_generic_to_shared(p);
}
__device__ __forceinline__ void ldsm_x4(uint32_t (&r)[4], uint32_t addr) {
    asm volatile("ldmatrix.sync.aligned.m8n8.x4.shared.b16 {%0,%1,%2,%3}, [%4];"
                 : "=r"(r[0]), "=r"(r[1]), "=r"(r[2]), "=r"(r[3]) : "r"(addr));
}
__device__ __forceinline__ void ldsm_x4_t(uint32_t (&r)[4], uint32_t addr) {
    asm volatile("ldmatrix.sync.aligned.m8n8.x4.trans.shared.b16 {%0,%1,%2,%3}, [%4];"
                 : "=r"(r[0]), "=r"(r[1]), "=r"(r[2]), "=r"(r[3]) : "r"(addr));
}
__device__ __forceinline__ void mma_bf16(float (&d)[4], const uint32_t (&a)[4],
                                         uint32_t b0, uint32_t b1) {
    asm volatile("mma.sync.aligned.m16n8k16.row.col.f32.bf16.bf16.f32 "
                 "{%0,%1,%2,%3}, {%4,%5,%6,%7}, {%8,%9}, {%0,%1,%2,%3};"
                 : "+f"(d[0]), "+f"(d[1]), "+f"(d[2]), "+f"(d[3])
                 : "r"(a[0]), "r"(a[1]), "r"(a[2]), "r"(a[3]), "r"(b0), "r"(b1));
}
__device__ __forceinline__ float ex2(float x) {
    float y;
    asm("ex2.approx.ftz.f32 %0, %1;" : "=f"(y) : "f"(x));
    return y;
}
__device__ __forceinline__ uint32_t pack_hi(float f0, float f1, __nv_bfloat162& h2) {
    h2 = __floats2bfloat162_rn(f0, f1);
    return *(uint32_t*)&h2;
}
__device__ __forceinline__ uint32_t pack_lo(float f0, float f1, const __nv_bfloat162& h2) {
    __nv_bfloat162 l2 = __floats2bfloat162_rn(f0 - __bfloat162float(h2.x),
                                              f1 - __bfloat162float(h2.y));
    return *(uint32_t*)&l2;
}

// ---------------- ONE consolidated prep kernel -------------------------------
// Flat index over [3 input splits | 4 weight splits | mask->bias].
// Per-element math identical to the R9 split_f32 / mask_to_bias kernels.
struct PrepArgs {
    const float4* xin[3];
    __nv_bfloat162* xhi[3];
    __nv_bfloat162* xlo[3];
    const float4* win[4];
    __nv_bfloat162* whi[4];
    __nv_bfloat162* wlo[4];
    const int4* mk;
    __nv_bfloat162* bias;
};

__device__ __forceinline__ void do_split(const float4* __restrict__ x,
                                         __nv_bfloat162* __restrict__ hi,
                                         __nv_bfloat162* __restrict__ lo, int i)
{
    float4 v = x[i];
    __nv_bfloat162 h0, h1;
    uint32_t u0 = pack_hi(v.x, v.y, h0), u1 = pack_hi(v.z, v.w, h1);
    uint32_t l0 = pack_lo(v.x, v.y, h0), l1 = pack_lo(v.z, v.w, h1);
    *(uint32_t*)&hi[2 * i] = u0; *(uint32_t*)&hi[2 * i + 1] = u1;
    *(uint32_t*)&lo[2 * i] = l0; *(uint32_t*)&lo[2 * i + 1] = l1;
}

__global__ __launch_bounds__(256) void prep_all(PrepArgs p)
{
    int idx = blockIdx.x * blockDim.x + threadIdx.x;
    if (idx >= PREP_UNITS) return;
    if (idx < 3 * NX4) {
        int job = idx / NX4;            // compile-time divisor
        int i = idx - job * NX4;
        do_split(p.xin[job], p.xhi[job], p.xlo[job], i);
    } else if (idx < 3 * NX4 + 4 * NW4) {
        int r = idx - 3 * NX4;
        int job = r / NW4;
        int i = r - job * NW4;
        do_split(p.win[job], p.whi[job], p.wlo[job], i);
    } else {
        int i = idx - (3 * NX4 + 4 * NW4);
        int4 m = p.mk[i];
        p.bias[2 * i] = __floats2bfloat162_rn(m.x ? 0.f : -1e9f, m.y ? 0.f : -1e9f);
        p.bias[2 * i + 1] = __floats2bfloat162_rn(m.z ? 0.f : -1e9f, m.w ? 0.f : -1e9f);
    }
}

// ---------------- mma.sync GEMM (R9 form: 512 thr, 4x4 warps, 128x128) -------
#define KCH      64
#define NCHUNK   (DMODEL / KCH)
#define TILE_B   16384
#define STAGE_B  (4 * TILE_B)
#define GEMM_SMEM (2 * STAGE_B)

__global__ __launch_bounds__(512, 1) void gemm_mma(
    const __nv_bfloat16* __restrict__ xhi, const __nv_bfloat16* __restrict__ xlo,
    const __nv_bfloat16* __restrict__ whi, const __nv_bfloat16* __restrict__ wlo,
    const float* __restrict__ bias, float* __restrict__ C,
    __nv_bfloat16* __restrict__ Chi, __nv_bfloat16* __restrict__ Clo, float scale)
{
    extern __shared__ __align__(1024) char smem[];
    const uint32_t sb = smem_u32(smem);
    const int tid = threadIdx.x, wid = tid >> 5, lane = tid & 31;
    const int warp_m = wid >> 2, warp_n = wid & 3;
    const int bn = blockIdx.x * 128, bm = blockIdx.y * 128;

    float acc[2][4][4];
#pragma unroll
    for (int i = 0; i < 2; i++)
#pragma unroll
        for (int j = 0; j < 4; j++)
#pragma unroll
            for (int e = 0; e < 4; e++) acc[i][j][e] = 0.0f;

    const __nv_bfloat16* srcs[4] = {
        xhi + (size_t)bm * DMODEL, xlo + (size_t)bm * DMODEL,
        whi + (size_t)bn * DMODEL, wlo + (size_t)bn * DMODEL };

    auto load_chunk = [&](int chunk, int stage) {
        const int k0 = chunk * KCH;
        const uint32_t st = sb + stage * STAGE_B;
#pragma unroll
        for (int i = 0; i < 8; i++) {
            int idx = tid + i * 512;
            int a = idx >> 10, r = (idx >> 3) & 127, c8 = idx & 7;
            uint32_t boff = r * 128 + c8 * 16;
            uint32_t sw = boff ^ ((boff >> 3) & 0x70);
            const void* g = srcs[a] + (size_t)r * DMODEL + k0 + c8 * 8;
            asm volatile("cp.async.cg.shared.global [%0], [%1], 16;"
                         :: "r"(st + a * TILE_B + sw), "l"(g));
        }
        asm volatile("cp.async.commit_group;" ::: "memory");
    };

    load_chunk(0, 0);

    for (int i = 0; i < NCHUNK; i++) {
        if (i + 1 < NCHUNK) {
            load_chunk(i + 1, (i + 1) & 1);
            asm volatile("cp.async.wait_group 1;" ::: "memory");
        } else {
            asm volatile("cp.async.wait_group 0;" ::: "memory");
        }
        __syncthreads();

        const uint32_t st = sb + (i & 1) * STAGE_B;
#pragma unroll
        for (int ks = 0; ks < 4; ks++) {
            const int cb = ks * 32 + ((lane >> 4) << 4);
            uint32_t ah[2][4], al[2][4], wh[2][4], wl[2][4];
#pragma unroll
            for (int mi = 0; mi < 2; mi++) {
                int r = warp_m * 32 + mi * 16 + (lane & 15);
                uint32_t boff = r * 128 + cb;
                uint32_t sw = boff ^ ((boff >> 3) & 0x70);
                ldsm_x4(ah[mi], st + sw);
                ldsm_x4(al[mi], st + TILE_B + sw);
            }
#pragma unroll
            for (int np = 0; np < 2; np++) {
                int r = warp_n * 32 + np * 16 + (lane & 15);
                uint32_t boff = r * 128 + cb;
                uint32_t sw = boff ^ ((boff >> 3) & 0x70);
                ldsm_x4(wh[np], st + 2 * TILE_B + sw);
                ldsm_x4(wl[np], st + 3 * TILE_B + sw);
            }
#pragma unroll
            for (int mi = 0; mi < 2; mi++)
#pragma unroll
                for (int nj = 0; nj < 4; nj++) {
                    int np = nj >> 1, o = nj & 1;
                    mma_bf16(acc[mi][nj], ah[mi], wh[np][o], wh[np][o + 2]);
                    mma_bf16(acc[mi][nj], ah[mi], wl[np][o], wl[np][o + 2]);
                    mma_bf16(acc[mi][nj], al[mi], wh[np][o], wh[np][o + 2]);
                }
        }
        __syncthreads();
    }

    const int r0 = lane >> 2, c0 = (lane & 3) * 2;
#pragma unroll
    for (int mi = 0; mi < 2; mi++) {
#pragma unroll
        for (int nj = 0; nj < 4; nj++) {
            int row = bm + warp_m * 32 + mi * 16 + r0;
            int col = bn + warp_n * 32 + nj * 8 + c0;
            float2 b2 = *(const float2*)&bias[col];
            float v0 = (acc[mi][nj][0] + b2.x) * scale;
            float v1 = (acc[mi][nj][1] + b2.y) * scale;
            float v2 = (acc[mi][nj][2] + b2.x) * scale;
            float v3 = (acc[mi][nj][3] + b2.y) * scale;
            if (Chi) {
                __nv_bfloat162 h0, h1;
                uint32_t u0 = pack_hi(v0, v1, h0), u1 = pack_hi(v2, v3, h1);
                uint32_t l0 = pack_lo(v0, v1, h0), l1 = pack_lo(v2, v3, h1);
                *(uint32_t*)&Chi[(size_t)row * DMODEL + col] = u0;
                *(uint32_t*)&Clo[(size_t)row * DMODEL + col] = l0;
                *(uint32_t*)&Chi[(size_t)(row + 8) * DMODEL + col] = u1;
                *(uint32_t*)&Clo[(size_t)(row + 8) * DMODEL + col] = l1;
            } else {
                *(float2*)&C[(size_t)row * DMODEL + col] = make_float2(v0, v1);
                *(float2*)&C[(size_t)(row + 8) * DMODEL + col] = make_float2(v2, v3);
            }
        }
    }
}

// ---------------- flash attention (R6/R9 form) -------------------------------
#define FA_STAGE 49152
#define FA_SMEM  (2 * FA_STAGE)
#define NBLK     (SLEN / 64)

__global__ __launch_bounds__(256, 1) void flash_attn_mma(
    const __nv_bfloat16* __restrict__ Qhi, const __nv_bfloat16* __restrict__ Qlo,
    const __nv_bfloat16* __restrict__ Khi, const __nv_bfloat16* __restrict__ Klo,
    const __nv_bfloat16* __restrict__ Vhi, const __nv_bfloat16* __restrict__ Vlo,
    const __nv_bfloat16* __restrict__ bias,
    __nv_bfloat16* __restrict__ Ahi, __nv_bfloat16* __restrict__ Alo)
{
    extern __shared__ __align__(1024) char smem[];
    const uint32_t sb = smem_u32(smem);
    const int tid = threadIdx.x, wid = tid >> 5, lane = tid & 31;
    const int q0 = blockIdx.x * 128, h = blockIdx.y, b = blockIdx.z;

    const size_t tok0 = (size_t)b * SLEN;
    const size_t hoff = (size_t)h * DKH;
    const int qr = q0 + wid * 16 + (lane >> 2);

    uint32_t qh[4][4], ql[4][4];
    {
        const size_t b0 = (tok0 + qr) * DMODEL + hoff;
        const size_t b1 = (tok0 + qr + 8) * DMODEL + hoff;
#pragma unroll
        for (int t = 0; t < 4; t++) {
            int c = t * 16 + 2 * (lane & 3);
            qh[t][0] = *(const uint32_t*)&Qhi[b0 + c];
            qh[t][1] = *(const uint32_t*)&Qhi[b1 + c];
            qh[t][2] = *(const uint32_t*)&Qhi[b0 + c + 8];
            qh[t][3] = *(const uint32_t*)&Qhi[b1 + c + 8];
            ql[t][0] = *(const uint32_t*)&Qlo[b0 + c];
            ql[t][1] = *(const uint32_t*)&Qlo[b1 + c];
            ql[t][2] = *(const uint32_t*)&Qlo[b0 + c + 8];
            ql[t][3] = *(const uint32_t*)&Qlo[b1 + c + 8];
        }
    }

    const __nv_bfloat16* srcs[4] = {
        Khi + tok0 * DMODEL + hoff, Klo + tok0 * DMODEL + hoff,
        Vhi + tok0 * DMODEL + hoff, Vlo + tok0 * DMODEL + hoff };
    const __nv_bfloat16* brow = bias + (tok0 + q0) * SLEN;

    auto load_kv = [&](int blk, int stage) {
        const int k0 = blk * 64;
        const uint32_t st = sb + stage * FA_STAGE;
#pragma unroll
        for (int i = 0; i < 8; i++) {
            int idx = tid + i * 256;
            int a = idx >> 9, r = (idx >> 3) & 63, c8 = idx & 7;
            uint32_t boff = r * 128 + c8 * 16;
            uint32_t sw = boff ^ ((boff >> 3) & 0x70);
            const void* g = srcs[a] + (size_t)(k0 + r) * DMODEL + c8 * 8;
            asm volatile("cp.async.cg.shared.global [%0], [%1], 16;"
                         :: "r"(st + a * 8192 + sw), "l"(g));
        }
#pragma unroll
        for (int i = 0; i < 4; i++) {
            int idx = tid + i * 256;
            int r = idx >> 3, c8 = idx & 7;
            uint32_t boff = r * 128 + c8 * 16;
            uint32_t sw = boff ^ ((boff >> 3) & 0x70);
            const void* g = brow + (size_t)r * SLEN + k0 + c8 * 8;
            asm volatile("cp.async.cg.shared.global [%0], [%1], 16;"
                         :: "r"(st + 32768 + sw), "l"(g));
        }
        asm volatile("cp.async.commit_group;" ::: "memory");
    };

    float l[2] = { 0.f, 0.f };
    float o[8][4];
#pragma unroll
    for (int j = 0; j < 8; j++)
#pragma unroll
        for (int e = 0; e < 4; e++) o[j][e] = 0.f;

    load_kv(0, 0);

    for (int blk = 0; blk < NBLK; blk++) {
        if (blk + 1 < NBLK) {
            load_kv(blk + 1, (blk + 1) & 1);
            asm volatile("cp.async.wait_group 1;" ::: "memory");
        } else {
            asm volatile("cp.async.wait_group 0;" ::: "memory");
        }
        __syncthreads();
        const uint32_t st = sb + (blk & 1) * FA_STAGE;

        float S[8][4];
#pragma unroll
        for (int j = 0; j < 8; j++)
#pragma unroll
            for (int e = 0; e < 4; e++) S[j][e] = 0.f;

#pragma unroll
        for (int t = 0; t < 4; t++) {
            const int cb = t * 32 + ((lane >> 4) << 4);
#pragma unroll
            for (int np = 0; np < 4; np++) {
                int r = np * 16 + (lane & 15);
                uint32_t boff = r * 128 + cb;
                uint32_t sw = boff ^ ((boff >> 3) & 0x70);
                uint32_t kh[4], kl[4];
                ldsm_x4(kh, st + sw);
                ldsm_x4(kl, st + 8192 + sw);
#pragma unroll
                for (int o2 = 0; o2 < 2; o2++) {
                    int j = np * 2 + o2;
                    mma_bf16(S[j], qh[t], kh[o2], kh[o2 + 2]);
                    mma_bf16(S[j], qh[t], kl[o2], kl[o2 + 2]);
                    mma_bf16(S[j], ql[t], kh[o2], kh[o2 + 2]);
                }
            }
        }

#pragma unroll
        for (int j2 = 0; j2 < 4; j2++) {
            uint32_t bf[4];
            int rr = wid * 16 + ((lane >> 3) & 1) * 8 + (lane & 7);
            int cc = (j2 * 2 + (lane >> 4)) * 16;
            uint32_t boff = rr * 128 + cc;
            uint32_t sw = boff ^ ((boff >> 3) & 0x70);
            ldsm_x4(bf, st + 32768 + sw);
            float2 f;
            f = __bfloat1622float2(*(__nv_bfloat162*)&bf[0]);
            S[2 * j2][0] += f.x; S[2 * j2][1] += f.y;
            f = __bfloat1622float2(*(__nv_bfloat162*)&bf[1]);
            S[2 * j2][2] += f.x; S[2 * j2][3] += f.y;
            f = __bfloat1622float2(*(__nv_bfloat162*)&bf[2]);
            S[2 * j2 + 1][0] += f.x; S[2 * j2 + 1][1] += f.y;
            f = __bfloat1622float2(*(__nv_bfloat162*)&bf[3]);
            S[2 * j2 + 1][2] += f.x; S[2 * j2 + 1][3] += f.y;
        }
#pragma unroll
        for (int j = 0; j < 8; j++) {
            S[j][0] = ex2(S[j][0]); S[j][1] = ex2(S[j][1]);
            S[j][2] = ex2(S[j][2]); S[j][3] = ex2(S[j][3]);
            l[0] += S[j][0] + S[j][1];
            l[1] += S[j][2] + S[j][3];
        }

#pragma unroll
        for (int t = 0; t < 4; t++) {
            uint32_t ph[4], pl[4];
            {
                __nv_bfloat162 h2;
                ph[0] = pack_hi(S[2 * t][0], S[2 * t][1], h2);
                pl[0] = pack_lo(S[2 * t][0], S[2 * t][1], h2);
                ph[1] = pack_hi(S[2 * t][2], S[2 * t][3], h2);
                pl[1] = pack_lo(S[2 * t][2], S[2 * t][3], h2);
                ph[2] = pack_hi(S[2 * t + 1][0], S[2 * t + 1][1], h2);
                pl[2] = pack_lo(S[2 * t + 1][0], S[2 * t + 1][1], h2);
                ph[3] = pack_hi(S[2 * t + 1][2], S[2 * t + 1][3], h2);
                pl[3] = pack_lo(S[2 * t + 1][2], S[2 * t + 1][3], h2);
            }
            const int vkey = t * 16 + ((lane >> 3) & 1) * 8 + (lane & 7);
#pragma unroll
            for (int g = 0; g < 4; g++) {
                int dcol = g * 16 + ((lane >> 4) & 1) * 8;
                uint32_t boff = vkey * 128 + dcol * 2;
                uint32_t sw = boff ^ ((boff >> 3) & 0x70);
                uint32_t vh[4], vl[4];
                ldsm_x4_t(vh, st + 16384 + sw);
                ldsm_x4_t(vl, st + 24576 + sw);
#pragma unroll
                for (int o2 = 0; o2 < 2; o2++) {
                    int j = g * 2 + o2;
                    mma_bf16(o[j], ph, vh[o2 * 2], vh[o2 * 2 + 1]);
                    mma_bf16(o[j], ph, vl[o2 * 2], vl[o2 * 2 + 1]);
                    mma_bf16(o[j], pl, vh[o2 * 2], vh[o2 * 2 + 1]);
                }
            }
        }
        __syncthreads();
    }

    l[0] += __shfl_xor_sync(0xffffffffu, l[0], 1);
    l[0] += __shfl_xor_sync(0xffffffffu, l[0], 2);
    l[1] += __shfl_xor_sync(0xffffffffu, l[1], 1);
    l[1] += __shfl_xor_sync(0xffffffffu, l[1], 2);
    const float i0 = 1.f / l[0], i1 = 1.f / l[1];
#pragma unroll
    for (int j = 0; j < 8; j++) {
        int c = j * 8 + 2 * (lane & 3);
        size_t a0 = (tok0 + qr) * DMODEL + hoff + c;
        size_t a1 = (tok0 + qr + 8) * DMODEL + hoff + c;
        __nv_bfloat162 h2;
        float f0 = o[j][0] * i0, f1 = o[j][1] * i0;
        uint32_t u = pack_hi(f0, f1, h2), v = pack_lo(f0, f1, h2);
        *(uint32_t*)&Ahi[a0] = u; *(uint32_t*)&Alo[a0] = v;
        f0 = o[j][2] * i1; f1 = o[j][3] * i1;
        u = pack_hi(f0, f1, h2); v = pack_lo(f0, f1, h2);
        *(uint32_t*)&Ahi[a1] = u; *(uint32_t*)&Alo[a1] = v;
    }
}

// ---------------- launcher ---------------------------------------------------
extern "C" void kernel_launch(void* const* d_in, const int* in_sizes, int n_in,
                              void* d_out, int out_size)
{
    const float* query = (const float*)d_in[0];
    const float* key   = (const float*)d_in[1];
    const float* value = (const float*)d_in[2];
    const int*   mask  = (const int*)d_in[3];
    const float* Wq    = (const float*)d_in[4];
    const float* bq    = (const float*)d_in[5];
    const float* Wk    = (const float*)d_in[6];
    const float* bk    = (const float*)d_in[7];
    const float* Wv    = (const float*)d_in[8];
    const float* bv    = (const float*)d_in[9];
    const float* Wo    = (const float*)d_in[10];
    const float* bo    = (const float*)d_in[11];
    float* out = (float*)d_out;

    __nv_bfloat16 *qhi, *qlo, *khi, *klo, *vhi, *vlo, *ahi, *alo, *bb;
    __nv_bfloat16 *xh[3], *xl[3], *wh[4], *wl[4];
    cudaGetSymbolAddress((void**)&qhi, g_qhi);
    cudaGetSymbolAddress((void**)&qlo, g_qlo);
    cudaGetSymbolAddress((void**)&khi, g_khi);
    cudaGetSymbolAddress((void**)&klo, g_klo);
    cudaGetSymbolAddress((void**)&vhi, g_vhi);
    cudaGetSymbolAddress((void**)&vlo, g_vlo);
    cudaGetSymbolAddress((void**)&ahi, g_ahi);
    cudaGetSymbolAddress((void**)&alo, g_alo);
    cudaGetSymbolAddress((void**)&bb,  g_bias);
    {
        __nv_bfloat16 *p;
        cudaGetSymbolAddress((void**)&p, g_xh);
        for (int i = 0; i < 3; i++) xh[i] = p + (size_t)i * MROWS * DMODEL;
        cudaGetSymbolAddress((void**)&p, g_xl);
        for (int i = 0; i < 3; i++) xl[i] = p + (size_t)i * MROWS * DMODEL;
        cudaGetSymbolAddress((void**)&p, g_wh);
        for (int i = 0; i < 4; i++) wh[i] = p + (size_t)i * DMODEL * DMODEL;
        cudaGetSymbolAddress((void**)&p, g_wl);
        for (int i = 0; i < 4; i++) wl[i] = p + (size_t)i * DMODEL * DMODEL;
    }

    cudaFuncSetAttribute(gemm_mma, cudaFuncAttributeMaxDynamicSharedMemorySize, GEMM_SMEM);
    cudaFuncSetAttribute(flash_attn_mma, cudaFuncAttributeMaxDynamicSharedMemorySize, FA_SMEM);

    // ---- one consolidated prep launch ----
    {
        PrepArgs p{};
        p.xin[0] = (const float4*)query;
        p.xin[1] = (const float4*)key;
        p.xin[2] = (const float4*)value;
        for (int i = 0; i < 3; i++) {
            p.xhi[i] = (__nv_bfloat162*)xh[i];
            p.xlo[i] = (__nv_bfloat162*)xl[i];
        }
        const float* Ws[4] = { Wq, Wk, Wv, Wo };
        for (int i = 0; i < 4; i++) {
            p.win[i] = (const float4*)Ws[i];
            p.whi[i] = (__nv_bfloat162*)wh[i];
            p.wlo[i] = (__nv_bfloat162*)wl[i];
        }
        p.mk = (const int4*)mask;
        p.bias = (__nv_bfloat162*)bb;
        prep_all<<<(PREP_UNITS + 255) / 256, 256>>>(p);
    }

    const float QSCALE = 0.125f * 1.4426950408889634f;
    dim3 gg(DMODEL / 128, MROWS / 128);   // (8, 32) — 256 CTAs, 512 threads

    gemm_mma<<<gg, 512, GEMM_SMEM>>>(xh[0], xl[0], wh[0], wl[0], bq,
                                     nullptr, qhi, qlo, QSCALE);
    gemm_mma<<<gg, 512, GEMM_SMEM>>>(xh[1], xl[1], wh[1], wl[1], bk,
                                     nullptr, khi, klo, 1.f);
    gemm_mma<<<gg, 512, GEMM_SMEM>>>(xh[2], xl[2], wh[2], wl[2], bv,
                                     nullptr, vhi, vlo, 1.f);

    dim3 fg(SLEN / 128, NHEAD, BATCH);   // (16, 16, 2)
    flash_attn_mma<<<fg, 256, FA_SMEM>>>(qhi, qlo, khi, klo, vhi, vlo, bb, ahi, alo);

    gemm_mma<<<gg, 512, GEMM_SMEM>>>(ahi, alo, wh[3], wl[3], bo,
                                     out, nullptr, nullptr, 1.f);
}

// round 15
// speedup vs baseline: 1.0358x; 1.0146x over previous
#include <cuda_runtime.h>
#include <cuda_bf16.h>
#include <cstdint>

#define BATCH  2
#define SLEN   2048
#define DMODEL 1024
#define NHEAD  16
#define DKH    64
#define MROWS  (BATCH * SLEN)   // 4096

#define NX4  (MROWS * DMODEL / 4)
#define NW4  (DMODEL * DMODEL / 4)
#define NB4  (BATCH * SLEN * SLEN / 4)
#define PREP_UNITS (3 * NX4 + 4 * NW4 + NB4)

// ---------------- scratch (allocation-free rule: __device__ globals) --------
__device__ __align__(16) __nv_bfloat16 g_xh[3][MROWS * DMODEL];
__device__ __align__(16) __nv_bfloat16 g_xl[3][MROWS * DMODEL];
__device__ __align__(16) __nv_bfloat16 g_qhi[MROWS * DMODEL];
__device__ __align__(16) __nv_bfloat16 g_qlo[MROWS * DMODEL];
__device__ __align__(16) __nv_bfloat16 g_khi[MROWS * DMODEL];
__device__ __align__(16) __nv_bfloat16 g_klo[MROWS * DMODEL];
__device__ __align__(16) __nv_bfloat16 g_vhi[MROWS * DMODEL];
__device__ __align__(16) __nv_bfloat16 g_vlo[MROWS * DMODEL];
__device__ __align__(16) __nv_bfloat16 g_ahi[MROWS * DMODEL];
__device__ __align__(16) __nv_bfloat16 g_alo[MROWS * DMODEL];
__device__ __align__(16) __nv_bfloat16 g_wh[4][DMODEL * DMODEL];
__device__ __align__(16) __nv_bfloat16 g_wl[4][DMODEL * DMODEL];
__device__ __align__(16) __nv_bfloat16 g_bias[(size_t)BATCH * SLEN * SLEN];

// ---------------- helpers ----------------------------------------------------
__device__ __forceinline__ uint32_t smem_u32(const void* p) {
    return (uint32_t)__cvta_generic_to_shared(p);
}
__device__ __forceinline__ void ldsm_x4(uint32_t (&r)[4], uint32_t addr) {
    asm volatile("ldmatrix.sync.aligned.m8n8.x4.shared.b16 {%0,%1,%2,%3}, [%4];"
                 : "=r"(r[0]), "=r"(r[1]), "=r"(r[2]), "=r"(r[3]) : "r"(addr));
}
__device__ __forceinline__ void ldsm_x4_t(uint32_t (&r)[4], uint32_t addr) {
    asm volatile("ldmatrix.sync.aligned.m8n8.x4.trans.shared.b16 {%0,%1,%2,%3}, [%4];"
                 : "=r"(r[0]), "=r"(r[1]), "=r"(r[2]), "=r"(r[3]) : "r"(addr));
}
__device__ __forceinline__ void mma_bf16(float (&d)[4], const uint32_t (&a)[4],
                                         uint32_t b0, uint32_t b1) {
    asm volatile("mma.sync.aligned.m16n8k16.row.col.f32.bf16.bf16.f32 "
                 "{%0,%1,%2,%3}, {%4,%5,%6,%7}, {%8,%9}, {%0,%1,%2,%3};"
                 : "+f"(d[0]), "+f"(d[1]), "+f"(d[2]), "+f"(d[3])
                 : "r"(a[0]), "r"(a[1]), "r"(a[2]), "r"(a[3]), "r"(b0), "r"(b1));
}
__device__ __forceinline__ float ex2(float x) {
    float y;
    asm("ex2.approx.ftz.f32 %0, %1;" : "=f"(y) : "f"(x));
    return y;
}
__device__ __forceinline__ uint32_t pack_hi(float f0, float f1, __nv_bfloat162& h2) {
    h2 = __floats2bfloat162_rn(f0, f1);
    return *(uint32_t*)&h2;
}
__device__ __forceinline__ uint32_t pack_lo(float f0, float f1, const __nv_bfloat162& h2) {
    __nv_bfloat162 l2 = __floats2bfloat162_rn(f0 - __bfloat162float(h2.x),
                                              f1 - __bfloat162float(h2.y));
    return *(uint32_t*)&l2;
}

// ---------------- ONE consolidated prep kernel (R14 form) --------------------
struct PrepArgs {
    const float4* xin[3];
    __nv_bfloat162* xhi[3];
    __nv_bfloat162* xlo[3];
    const float4* win[4];
    __nv_bfloat162* whi[4];
    __nv_bfloat162* wlo[4];
    const int4* mk;
    __nv_bfloat162* bias;
};

__device__ __forceinline__ void do_split(const float4* __restrict__ x,
                                         __nv_bfloat162* __restrict__ hi,
                                         __nv_bfloat162* __restrict__ lo, int i)
{
    float4 v = x[i];
    __nv_bfloat162 h0, h1;
    uint32_t u0 = pack_hi(v.x, v.y, h0), u1 = pack_hi(v.z, v.w, h1);
    uint32_t l0 = pack_lo(v.x, v.y, h0), l1 = pack_lo(v.z, v.w, h1);
    *(uint32_t*)&hi[2 * i] = u0; *(uint32_t*)&hi[2 * i + 1] = u1;
    *(uint32_t*)&lo[2 * i] = l0; *(uint32_t*)&lo[2 * i + 1] = l1;
}

__global__ __launch_bounds__(256) void prep_all(PrepArgs p)
{
    int idx = blockIdx.x * blockDim.x + threadIdx.x;
    if (idx >= PREP_UNITS) return;
    if (idx < 3 * NX4) {
        int job = idx / NX4;
        int i = idx - job * NX4;
        do_split(p.xin[job], p.xhi[job], p.xlo[job], i);
    } else if (idx < 3 * NX4 + 4 * NW4) {
        int r = idx - 3 * NX4;
        int job = r / NW4;
        int i = r - job * NW4;
        do_split(p.win[job], p.whi[job], p.wlo[job], i);
    } else {
        int i = idx - (3 * NX4 + 4 * NW4);
        int4 m = p.mk[i];
        p.bias[2 * i] = __floats2bfloat162_rn(m.x ? 0.f : -1e9f, m.y ? 0.f : -1e9f);
        p.bias[2 * i + 1] = __floats2bfloat162_rn(m.z ? 0.f : -1e9f, m.w ? 0.f : -1e9f);
    }
}

// ---------------- mma.sync GEMM (R14 form) -----------------------------------
#define KCH      64
#define NCHUNK   (DMODEL / KCH)
#define TILE_B   16384
#define STAGE_B  (4 * TILE_B)
#define GEMM_SMEM (2 * STAGE_B)

__global__ __launch_bounds__(512, 1) void gemm_mma(
    const __nv_bfloat16* __restrict__ xhi, const __nv_bfloat16* __restrict__ xlo,
    const __nv_bfloat16* __restrict__ whi, const __nv_bfloat16* __restrict__ wlo,
    const float* __restrict__ bias, float* __restrict__ C,
    __nv_bfloat16* __restrict__ Chi, __nv_bfloat16* __restrict__ Clo, float scale)
{
    extern __shared__ __align__(1024) char smem[];
    const uint32_t sb = smem_u32(smem);
    const int tid = threadIdx.x, wid = tid >> 5, lane = tid & 31;
    const int warp_m = wid >> 2, warp_n = wid & 3;
    const int bn = blockIdx.x * 128, bm = blockIdx.y * 128;

    float acc[2][4][4];
#pragma unroll
    for (int i = 0; i < 2; i++)
#pragma unroll
        for (int j = 0; j < 4; j++)
#pragma unroll
            for (int e = 0; e < 4; e++) acc[i][j][e] = 0.0f;

    const __nv_bfloat16* srcs[4] = {
        xhi + (size_t)bm * DMODEL, xlo + (size_t)bm * DMODEL,
        whi + (size_t)bn * DMODEL, wlo + (size_t)bn * DMODEL };

    auto load_chunk = [&](int chunk, int stage) {
        const int k0 = chunk * KCH;
        const uint32_t st = sb + stage * STAGE_B;
#pragma unroll
        for (int i = 0; i < 8; i++) {
            int idx = tid + i * 512;
            int a = idx >> 10, r = (idx >> 3) & 127, c8 = idx & 7;
            uint32_t boff = r * 128 + c8 * 16;
            uint32_t sw = boff ^ ((boff >> 3) & 0x70);
            const void* g = srcs[a] + (size_t)r * DMODEL + k0 + c8 * 8;
            asm volatile("cp.async.cg.shared.global [%0], [%1], 16;"
                         :: "r"(st + a * TILE_B + sw), "l"(g));
        }
        asm volatile("cp.async.commit_group;" ::: "memory");
    };

    load_chunk(0, 0);

    for (int i = 0; i < NCHUNK; i++) {
        if (i + 1 < NCHUNK) {
            load_chunk(i + 1, (i + 1) & 1);
            asm volatile("cp.async.wait_group 1;" ::: "memory");
        } else {
            asm volatile("cp.async.wait_group 0;" ::: "memory");
        }
        __syncthreads();

        const uint32_t st = sb + (i & 1) * STAGE_B;
#pragma unroll
        for (int ks = 0; ks < 4; ks++) {
            const int cb = ks * 32 + ((lane >> 4) << 4);
            uint32_t ah[2][4], al[2][4], wh[2][4], wl[2][4];
#pragma unroll
            for (int mi = 0; mi < 2; mi++) {
                int r = warp_m * 32 + mi * 16 + (lane & 15);
                uint32_t boff = r * 128 + cb;
                uint32_t sw = boff ^ ((boff >> 3) & 0x70);
                ldsm_x4(ah[mi], st + sw);
                ldsm_x4(al[mi], st + TILE_B + sw);
            }
#pragma unroll
            for (int np = 0; np < 2; np++) {
                int r = warp_n * 32 + np * 16 + (lane & 15);
                uint32_t boff = r * 128 + cb;
                uint32_t sw = boff ^ ((boff >> 3) & 0x70);
                ldsm_x4(wh[np], st + 2 * TILE_B + sw);
                ldsm_x4(wl[np], st + 3 * TILE_B + sw);
            }
#pragma unroll
            for (int mi = 0; mi < 2; mi++)
#pragma unroll
                for (int nj = 0; nj < 4; nj++) {
                    int np = nj >> 1, o = nj & 1;
                    mma_bf16(acc[mi][nj], ah[mi], wh[np][o], wh[np][o + 2]);
                    mma_bf16(acc[mi][nj], ah[mi], wl[np][o], wl[np][o + 2]);
                    mma_bf16(acc[mi][nj], al[mi], wh[np][o], wh[np][o + 2]);
                }
        }
        __syncthreads();
    }

    const int r0 = lane >> 2, c0 = (lane & 3) * 2;
#pragma unroll
    for (int mi = 0; mi < 2; mi++) {
#pragma unroll
        for (int nj = 0; nj < 4; nj++) {
            int row = bm + warp_m * 32 + mi * 16 + r0;
            int col = bn + warp_n * 32 + nj * 8 + c0;
            float2 b2 = *(const float2*)&bias[col];
            float v0 = (acc[mi][nj][0] + b2.x) * scale;
            float v1 = (acc[mi][nj][1] + b2.y) * scale;
            float v2 = (acc[mi][nj][2] + b2.x) * scale;
            float v3 = (acc[mi][nj][3] + b2.y) * scale;
            if (Chi) {
                __nv_bfloat162 h0, h1;
                uint32_t u0 = pack_hi(v0, v1, h0), u1 = pack_hi(v2, v3, h1);
                uint32_t l0 = pack_lo(v0, v1, h0), l1 = pack_lo(v2, v3, h1);
                *(uint32_t*)&Chi[(size_t)row * DMODEL + col] = u0;
                *(uint32_t*)&Clo[(size_t)row * DMODEL + col] = l0;
                *(uint32_t*)&Chi[(size_t)(row + 8) * DMODEL + col] = u1;
                *(uint32_t*)&Clo[(size_t)(row + 8) * DMODEL + col] = l1;
            } else {
                *(float2*)&C[(size_t)row * DMODEL + col] = make_float2(v0, v1);
                *(float2*)&C[(size_t)(row + 8) * DMODEL + col] = make_float2(v2, v3);
            }
        }
    }
}

// ---------------- flash attention: Bc=128 (two 64-key sub-stages/stage) ------
#define FA_SUB   49152                  // 64-key sub-stage: K,V hi/lo (4x8KB) + bias 16KB
#define FA_STAGE (2 * FA_SUB)           // 128 keys
#define FA_SMEM  (2 * FA_STAGE)         // 196608
#define NBLK128  (SLEN / 128)           // 16

__global__ __launch_bounds__(256, 1) void flash_attn_mma(
    const __nv_bfloat16* __restrict__ Qhi, const __nv_bfloat16* __restrict__ Qlo,
    const __nv_bfloat16* __restrict__ Khi, const __nv_bfloat16* __restrict__ Klo,
    const __nv_bfloat16* __restrict__ Vhi, const __nv_bfloat16* __restrict__ Vlo,
    const __nv_bfloat16* __restrict__ bias,
    __nv_bfloat16* __restrict__ Ahi, __nv_bfloat16* __restrict__ Alo)
{
    extern __shared__ __align__(1024) char smem[];
    const uint32_t sb = smem_u32(smem);
    const int tid = threadIdx.x, wid = tid >> 5, lane = tid & 31;
    const int q0 = blockIdx.x * 128, h = blockIdx.y, b = blockIdx.z;

    const size_t tok0 = (size_t)b * SLEN;
    const size_t hoff = (size_t)h * DKH;
    const int qr = q0 + wid * 16 + (lane >> 2);

    uint32_t qh[4][4], ql[4][4];
    {
        const size_t b0 = (tok0 + qr) * DMODEL + hoff;
        const size_t b1 = (tok0 + qr + 8) * DMODEL + hoff;
#pragma unroll
        for (int t = 0; t < 4; t++) {
            int c = t * 16 + 2 * (lane & 3);
            qh[t][0] = *(const uint32_t*)&Qhi[b0 + c];
            qh[t][1] = *(const uint32_t*)&Qhi[b1 + c];
            qh[t][2] = *(const uint32_t*)&Qhi[b0 + c + 8];
            qh[t][3] = *(const uint32_t*)&Qhi[b1 + c + 8];
            ql[t][0] = *(const uint32_t*)&Qlo[b0 + c];
            ql[t][1] = *(const uint32_t*)&Qlo[b1 + c];
            ql[t][2] = *(const uint32_t*)&Qlo[b0 + c + 8];
            ql[t][3] = *(const uint32_t*)&Qlo[b1 + c + 8];
        }
    }

    const __nv_bfloat16* srcs[4] = {
        Khi + tok0 * DMODEL + hoff, Klo + tok0 * DMODEL + hoff,
        Vhi + tok0 * DMODEL + hoff, Vlo + tok0 * DMODEL + hoff };
    const __nv_bfloat16* brow = bias + (tok0 + q0) * SLEN;

    // Loads 64 keys into one sub-stage (layout identical to R14's stage).
    auto load_sub = [&](int k0, uint32_t st) {
#pragma unroll
        for (int i = 0; i < 8; i++) {
            int idx = tid + i * 256;
            int a = idx >> 9, r = (idx >> 3) & 63, c8 = idx & 7;
            uint32_t boff = r * 128 + c8 * 16;
            uint32_t sw = boff ^ ((boff >> 3) & 0x70);
            const void* g = srcs[a] + (size_t)(k0 + r) * DMODEL + c8 * 8;
            asm volatile("cp.async.cg.shared.global [%0], [%1], 16;"
                         :: "r"(st + a * 8192 + sw), "l"(g));
        }
#pragma unroll
        for (int i = 0; i < 4; i++) {
            int idx = tid + i * 256;
            int r = idx >> 3, c8 = idx & 7;
            uint32_t boff = r * 128 + c8 * 16;
            uint32_t sw = boff ^ ((boff >> 3) & 0x70);
            const void* g = brow + (size_t)r * SLEN + k0 + c8 * 8;
            asm volatile("cp.async.cg.shared.global [%0], [%1], 16;"
                         :: "r"(st + 32768 + sw), "l"(g));
        }
    };
    auto load_kv128 = [&](int blk, int stage) {
        const uint32_t st = sb + stage * FA_STAGE;
        load_sub(blk * 128, st);
        load_sub(blk * 128 + 64, st + FA_SUB);
        asm volatile("cp.async.commit_group;" ::: "memory");
    };

    float l[2] = { 0.f, 0.f };
    float o[8][4];
#pragma unroll
    for (int j = 0; j < 8; j++)
#pragma unroll
        for (int e = 0; e < 4; e++) o[j][e] = 0.f;

    load_kv128(0, 0);

    for (int blk = 0; blk < NBLK128; blk++) {
        if (blk + 1 < NBLK128) {
            load_kv128(blk + 1, (blk + 1) & 1);
            asm volatile("cp.async.wait_group 1;" ::: "memory");
        } else {
            asm volatile("cp.async.wait_group 0;" ::: "memory");
        }
        __syncthreads();

#pragma unroll
        for (int half = 0; half < 2; half++) {
            const uint32_t st = sb + (blk & 1) * FA_STAGE + half * FA_SUB;

            float S[8][4];
#pragma unroll
            for (int j = 0; j < 8; j++)
#pragma unroll
                for (int e = 0; e < 4; e++) S[j][e] = 0.f;

#pragma unroll
            for (int t = 0; t < 4; t++) {
                const int cb = t * 32 + ((lane >> 4) << 4);
#pragma unroll
                for (int np = 0; np < 4; np++) {
                    int r = np * 16 + (lane & 15);
                    uint32_t boff = r * 128 + cb;
                    uint32_t sw = boff ^ ((boff >> 3) & 0x70);
                    uint32_t kh[4], kl[4];
                    ldsm_x4(kh, st + sw);
                    ldsm_x4(kl, st + 8192 + sw);
#pragma unroll
                    for (int o2 = 0; o2 < 2; o2++) {
                        int j = np * 2 + o2;
                        mma_bf16(S[j], qh[t], kh[o2], kh[o2 + 2]);
                        mma_bf16(S[j], qh[t], kl[o2], kl[o2 + 2]);
                        mma_bf16(S[j], ql[t], kh[o2], kh[o2 + 2]);
                    }
                }
            }

#pragma unroll
            for (int j2 = 0; j2 < 4; j2++) {
                uint32_t bf[4];
                int rr = wid * 16 + ((lane >> 3) & 1) * 8 + (lane & 7);
                int cc = (j2 * 2 + (lane >> 4)) * 16;
                uint32_t boff = rr * 128 + cc;
                uint32_t sw = boff ^ ((boff >> 3) & 0x70);
                ldsm_x4(bf, st + 32768 + sw);
                float2 f;
                f = __bfloat1622float2(*(__nv_bfloat162*)&bf[0]);
                S[2 * j2][0] += f.x; S[2 * j2][1] += f.y;
                f = __bfloat1622float2(*(__nv_bfloat162*)&bf[1]);
                S[2 * j2][2] += f.x; S[2 * j2][3] += f.y;
                f = __bfloat1622float2(*(__nv_bfloat162*)&bf[2]);
                S[2 * j2 + 1][0] += f.x; S[2 * j2 + 1][1] += f.y;
                f = __bfloat1622float2(*(__nv_bfloat162*)&bf[3]);
                S[2 * j2 + 1][2] += f.x; S[2 * j2 + 1][3] += f.y;
            }
#pragma unroll
            for (int j = 0; j < 8; j++) {
                S[j][0] = ex2(S[j][0]); S[j][1] = ex2(S[j][1]);
                S[j][2] = ex2(S[j][2]); S[j][3] = ex2(S[j][3]);
                l[0] += S[j][0] + S[j][1];
                l[1] += S[j][2] + S[j][3];
            }

#pragma unroll
            for (int t = 0; t < 4; t++) {
                uint32_t ph[4], pl[4];
                {
                    __nv_bfloat162 h2;
                    ph[0] = pack_hi(S[2 * t][0], S[2 * t][1], h2);
                    pl[0] = pack_lo(S[2 * t][0], S[2 * t][1], h2);
                    ph[1] = pack_hi(S[2 * t][2], S[2 * t][3], h2);
                    pl[1] = pack_lo(S[2 * t][2], S[2 * t][3], h2);
                    ph[2] = pack_hi(S[2 * t + 1][0], S[2 * t + 1][1], h2);
                    pl[2] = pack_lo(S[2 * t + 1][0], S[2 * t + 1][1], h2);
                    ph[3] = pack_hi(S[2 * t + 1][2], S[2 * t + 1][3], h2);
                    pl[3] = pack_lo(S[2 * t + 1][2], S[2 * t + 1][3], h2);
                }
                const int vkey = t * 16 + ((lane >> 3) & 1) * 8 + (lane & 7);
#pragma unroll
                for (int g = 0; g < 4; g++) {
                    int dcol = g * 16 + ((lane >> 4) & 1) * 8;
                    uint32_t boff = vkey * 128 + dcol * 2;
                    uint32_t sw = boff ^ ((boff >> 3) & 0x70);
                    uint32_t vh[4], vl[4];
                    ldsm_x4_t(vh, st + 16384 + sw);
                    ldsm_x4_t(vl, st + 24576 + sw);
#pragma unroll
                    for (int o2 = 0; o2 < 2; o2++) {
                        int j = g * 2 + o2;
                        mma_bf16(o[j], ph, vh[o2 * 2], vh[o2 * 2 + 1]);
                        mma_bf16(o[j], ph, vl[o2 * 2], vl[o2 * 2 + 1]);
                        mma_bf16(o[j], pl, vh[o2 * 2], vh[o2 * 2 + 1]);
                    }
                }
            }
        }
        __syncthreads();
    }

    l[0] += __shfl_xor_sync(0xffffffffu, l[0], 1);
    l[0] += __shfl_xor_sync(0xffffffffu, l[0], 2);
    l[1] += __shfl_xor_sync(0xffffffffu, l[1], 1);
    l[1] += __shfl_xor_sync(0xffffffffu, l[1], 2);
    const float i0 = 1.f / l[0], i1 = 1.f / l[1];
#pragma unroll
    for (int j = 0; j < 8; j++) {
        int c = j * 8 + 2 * (lane & 3);
        size_t a0 = (tok0 + qr) * DMODEL + hoff + c;
        size_t a1 = (tok0 + qr + 8) * DMODEL + hoff + c;
        __nv_bfloat162 h2;
        float f0 = o[j][0] * i0, f1 = o[j][1] * i0;
        uint32_t u = pack_hi(f0, f1, h2), v = pack_lo(f0, f1, h2);
        *(uint32_t*)&Ahi[a0] = u; *(uint32_t*)&Alo[a0] = v;
        f0 = o[j][2] * i1; f1 = o[j][3] * i1;
        u = pack_hi(f0, f1, h2); v = pack_lo(f0, f1, h2);
        *(uint32_t*)&Ahi[a1] = u; *(uint32_t*)&Alo[a1] = v;
    }
}

// ---------------- launcher ---------------------------------------------------
extern "C" void kernel_launch(void* const* d_in, const int* in_sizes, int n_in,
                              void* d_out, int out_size)
{
    const float* query = (const float*)d_in[0];
    const float* key   = (const float*)d_in[1];
    const float* value = (const float*)d_in[2];
    const int*   mask  = (const int*)d_in[3];
    const float* Wq    = (const float*)d_in[4];
    const float* bq    = (const float*)d_in[5];
    const float* Wk    = (const float*)d_in[6];
    const float* bk    = (const float*)d_in[7];
    const float* Wv    = (const float*)d_in[8];
    const float* bv    = (const float*)d_in[9];
    const float* Wo    = (const float*)d_in[10];
    const float* bo    = (const float*)d_in[11];
    float* out = (float*)d_out;

    __nv_bfloat16 *qhi, *qlo, *khi, *klo, *vhi, *vlo, *ahi, *alo, *bb;
    __nv_bfloat16 *xh[3], *xl[3], *wh[4], *wl[4];
    cudaGetSymbolAddress((void**)&qhi, g_qhi);
    cudaGetSymbolAddress((void**)&qlo, g_qlo);
    cudaGetSymbolAddress((void**)&khi, g_khi);
    cudaGetSymbolAddress((void**)&klo, g_klo);
    cudaGetSymbolAddress((void**)&vhi, g_vhi);
    cudaGetSymbolAddress((void**)&vlo, g_vlo);
    cudaGetSymbolAddress((void**)&ahi, g_ahi);
    cudaGetSymbolAddress((void**)&alo, g_alo);
    cudaGetSymbolAddress((void**)&bb,  g_bias);
    {
        __nv_bfloat16 *p;
        cudaGetSymbolAddress((void**)&p, g_xh);
        for (int i = 0; i < 3; i++) xh[i] = p + (size_t)i * MROWS * DMODEL;
        cudaGetSymbolAddress((void**)&p, g_xl);
        for (int i = 0; i < 3; i++) xl[i] = p + (size_t)i * MROWS * DMODEL;
        cudaGetSymbolAddress((void**)&p, g_wh);
        for (int i = 0; i < 4; i++) wh[i] = p + (size_t)i * DMODEL * DMODEL;
        cudaGetSymbolAddress((void**)&p, g_wl);
        for (int i = 0; i < 4; i++) wl[i] = p + (size_t)i * DMODEL * DMODEL;
    }

    cudaFuncSetAttribute(gemm_mma, cudaFuncAttributeMaxDynamicSharedMemorySize, GEMM_SMEM);
    cudaFuncSetAttribute(flash_attn_mma, cudaFuncAttributeMaxDynamicSharedMemorySize, FA_SMEM);

    {
        PrepArgs p{};
        p.xin[0] = (const float4*)query;
        p.xin[1] = (const float4*)key;
        p.xin[2] = (const float4*)value;
        for (int i = 0; i < 3; i++) {
            p.xhi[i] = (__nv_bfloat162*)xh[i];
            p.xlo[i] = (__nv_bfloat162*)xl[i];
        }
        const float* Ws[4] = { Wq, Wk, Wv, Wo };
        for (int i = 0; i < 4; i++) {
            p.win[i] = (const float4*)Ws[i];
            p.whi[i] = (__nv_bfloat162*)wh[i];
            p.wlo[i] = (__nv_bfloat162*)wl[i];
        }
        p.mk = (const int4*)mask;
        p.bias = (__nv_bfloat162*)bb;
        prep_all<<<(PREP_UNITS + 255) / 256, 256>>>(p);
    }

    const float QSCALE = 0.125f * 1.4426950408889634f;
    dim3 gg(DMODEL / 128, MROWS / 128);

    gemm_mma<<<gg, 512, GEMM_SMEM>>>(xh[0], xl[0], wh[0], wl[0], bq,
                                     nullptr, qhi, qlo, QSCALE);
    gemm_mma<<<gg, 512, GEMM_SMEM>>>(xh[1], xl[1], wh[1], wl[1], bk,
                                     nullptr, khi, klo, 1.f);
    gemm_mma<<<gg, 512, GEMM_SMEM>>>(xh[2], xl[2], wh[2], wl[2], bv,
                                     nullptr, vhi, vlo, 1.f);

    dim3 fg(SLEN / 128, NHEAD, BATCH);
    flash_attn_mma<<<fg, 256, FA_SMEM>>>(qhi, qlo, khi, klo, vhi, vlo, bb, ahi, alo);

    gemm_mma<<<gg, 512, GEMM_SMEM>>>(ahi, alo, wh[3], wl[3], bo,
                                     out, nullptr, nullptr, 1.f);
}

// round 16
// speedup vs baseline: 1.0480x; 1.0118x over previous
#include <cuda_runtime.h>
#include <cuda_bf16.h>
#include <cstdint>

#define BATCH  2
#define SLEN   2048
#define DMODEL 1024
#define NHEAD  16
#define DKH    64
#define MROWS  (BATCH * SLEN)   // 4096

#define NX4  (MROWS * DMODEL / 4)
#define NW4  (DMODEL * DMODEL / 4)
#define NB4  (BATCH * SLEN * SLEN / 4)
#define PREP_UNITS (3 * NX4 + 4 * NW4 + NB4)

// ---------------- scratch (allocation-free rule: __device__ globals) --------
__device__ __align__(16) __nv_bfloat16 g_xh[3][MROWS * DMODEL];
__device__ __align__(16) __nv_bfloat16 g_xl[3][MROWS * DMODEL];
__device__ __align__(16) __nv_bfloat16 g_qhi[MROWS * DMODEL];
__device__ __align__(16) __nv_bfloat16 g_qlo[MROWS * DMODEL];
__device__ __align__(16) __nv_bfloat16 g_khi[MROWS * DMODEL];
__device__ __align__(16) __nv_bfloat16 g_klo[MROWS * DMODEL];
__device__ __align__(16) __nv_bfloat16 g_vhi[MROWS * DMODEL];
__device__ __align__(16) __nv_bfloat16 g_vlo[MROWS * DMODEL];
__device__ __align__(16) __nv_bfloat16 g_ahi[MROWS * DMODEL];
__device__ __align__(16) __nv_bfloat16 g_alo[MROWS * DMODEL];
__device__ __align__(16) __nv_bfloat16 g_wh[4][DMODEL * DMODEL];
__device__ __align__(16) __nv_bfloat16 g_wl[4][DMODEL * DMODEL];
__device__ __align__(16) __nv_bfloat16 g_bias[(size_t)BATCH * SLEN * SLEN];

// ---------------- helpers ----------------------------------------------------
__device__ __forceinline__ uint32_t smem_u32(const void* p) {
    return (uint32_t)__cvta_generic_to_shared(p);
}
__device__ __forceinline__ void ldsm_x4(uint32_t (&r)[4], uint32_t addr) {
    asm volatile("ldmatrix.sync.aligned.m8n8.x4.shared.b16 {%0,%1,%2,%3}, [%4];"
                 : "=r"(r[0]), "=r"(r[1]), "=r"(r[2]), "=r"(r[3]) : "r"(addr));
}
__device__ __forceinline__ void ldsm_x4_t(uint32_t (&r)[4], uint32_t addr) {
    asm volatile("ldmatrix.sync.aligned.m8n8.x4.trans.shared.b16 {%0,%1,%2,%3}, [%4];"
                 : "=r"(r[0]), "=r"(r[1]), "=r"(r[2]), "=r"(r[3]) : "r"(addr));
}
__device__ __forceinline__ void mma_bf16(float (&d)[4], const uint32_t (&a)[4],
                                         uint32_t b0, uint32_t b1) {
    asm volatile("mma.sync.aligned.m16n8k16.row.col.f32.bf16.bf16.f32 "
                 "{%0,%1,%2,%3}, {%4,%5,%6,%7}, {%8,%9}, {%0,%1,%2,%3};"
                 : "+f"(d[0]), "+f"(d[1]), "+f"(d[2]), "+f"(d[3])
                 : "r"(a[0]), "r"(a[1]), "r"(a[2]), "r"(a[3]), "r"(b0), "r"(b1));
}
__device__ __forceinline__ float ex2(float x) {
    float y;
    asm("ex2.approx.ftz.f32 %0, %1;" : "=f"(y) : "f"(x));
    return y;
}
__device__ __forceinline__ uint32_t pack_hi(float f0, float f1, __nv_bfloat162& h2) {
    h2 = __floats2bfloat162_rn(f0, f1);
    return *(uint32_t*)&h2;
}
__device__ __forceinline__ uint32_t pack_lo(float f0, float f1, const __nv_bfloat162& h2) {
    __nv_bfloat162 l2 = __floats2bfloat162_rn(f0 - __bfloat162float(h2.x),
                                              f1 - __bfloat162float(h2.y));
    return *(uint32_t*)&l2;
}

// ---------------- ONE consolidated prep kernel (R14 form) --------------------
struct PrepArgs {
    const float4* xin[3];
    __nv_bfloat162* xhi[3];
    __nv_bfloat162* xlo[3];
    const float4* win[4];
    __nv_bfloat162* whi[4];
    __nv_bfloat162* wlo[4];
    const int4* mk;
    __nv_bfloat162* bias;
};

__device__ __forceinline__ void do_split(const float4* __restrict__ x,
                                         __nv_bfloat162* __restrict__ hi,
                                         __nv_bfloat162* __restrict__ lo, int i)
{
    float4 v = x[i];
    __nv_bfloat162 h0, h1;
    uint32_t u0 = pack_hi(v.x, v.y, h0), u1 = pack_hi(v.z, v.w, h1);
    uint32_t l0 = pack_lo(v.x, v.y, h0), l1 = pack_lo(v.z, v.w, h1);
    *(uint32_t*)&hi[2 * i] = u0; *(uint32_t*)&hi[2 * i + 1] = u1;
    *(uint32_t*)&lo[2 * i] = l0; *(uint32_t*)&lo[2 * i + 1] = l1;
}

__global__ __launch_bounds__(256) void prep_all(PrepArgs p)
{
    int idx = blockIdx.x * blockDim.x + threadIdx.x;
    if (idx >= PREP_UNITS) return;
    if (idx < 3 * NX4) {
        int job = idx / NX4;
        int i = idx - job * NX4;
        do_split(p.xin[job], p.xhi[job], p.xlo[job], i);
    } else if (idx < 3 * NX4 + 4 * NW4) {
        int r = idx - 3 * NX4;
        int job = r / NW4;
        int i = r - job * NW4;
        do_split(p.win[job], p.whi[job], p.wlo[job], i);
    } else {
        int i = idx - (3 * NX4 + 4 * NW4);
        int4 m = p.mk[i];
        p.bias[2 * i] = __floats2bfloat162_rn(m.x ? 0.f : -1e9f, m.y ? 0.f : -1e9f);
        p.bias[2 * i + 1] = __floats2bfloat162_rn(m.z ? 0.f : -1e9f, m.w ? 0.f : -1e9f);
    }
}

// ---------------- mma.sync GEMM (R15 body; optional grid.z batch) ------------
#define KCH      64
#define NCHUNK   (DMODEL / KCH)
#define TILE_B   16384
#define STAGE_B  (4 * TILE_B)
#define GEMM_SMEM (2 * STAGE_B)

struct GemmJobs {
    const __nv_bfloat16* xhi[3]; const __nv_bfloat16* xlo[3];
    const __nv_bfloat16* whi[3]; const __nv_bfloat16* wlo[3];
    const float* bias[3];
    float* C[3];
    __nv_bfloat16* Chi[3]; __nv_bfloat16* Clo[3];
    float scale[3];
};

__global__ __launch_bounds__(512, 1) void gemm_mma(GemmJobs jb)
{
    extern __shared__ __align__(1024) char smem[];
    const uint32_t sb = smem_u32(smem);
    const int z = blockIdx.z;
    const int tid = threadIdx.x, wid = tid >> 5, lane = tid & 31;
    const int warp_m = wid >> 2, warp_n = wid & 3;
    const int bn = blockIdx.x * 128, bm = blockIdx.y * 128;

    const float* bias = jb.bias[z];
    float* C = jb.C[z];
    __nv_bfloat16 *Chi = jb.Chi[z], *Clo = jb.Clo[z];
    const float scale = jb.scale[z];

    float acc[2][4][4];
#pragma unroll
    for (int i = 0; i < 2; i++)
#pragma unroll
        for (int j = 0; j < 4; j++)
#pragma unroll
            for (int e = 0; e < 4; e++) acc[i][j][e] = 0.0f;

    const __nv_bfloat16* srcs[4] = {
        jb.xhi[z] + (size_t)bm * DMODEL, jb.xlo[z] + (size_t)bm * DMODEL,
        jb.whi[z] + (size_t)bn * DMODEL, jb.wlo[z] + (size_t)bn * DMODEL };

    auto load_chunk = [&](int chunk, int stage) {
        const int k0 = chunk * KCH;
        const uint32_t st = sb + stage * STAGE_B;
#pragma unroll
        for (int i = 0; i < 8; i++) {
            int idx = tid + i * 512;
            int a = idx >> 10, r = (idx >> 3) & 127, c8 = idx & 7;
            uint32_t boff = r * 128 + c8 * 16;
            uint32_t sw = boff ^ ((boff >> 3) & 0x70);
            const void* g = srcs[a] + (size_t)r * DMODEL + k0 + c8 * 8;
            asm volatile("cp.async.cg.shared.global [%0], [%1], 16;"
                         :: "r"(st + a * TILE_B + sw), "l"(g));
        }
        asm volatile("cp.async.commit_group;" ::: "memory");
    };

    load_chunk(0, 0);

    for (int i = 0; i < NCHUNK; i++) {
        if (i + 1 < NCHUNK) {
            load_chunk(i + 1, (i + 1) & 1);
            asm volatile("cp.async.wait_group 1;" ::: "memory");
        } else {
            asm volatile("cp.async.wait_group 0;" ::: "memory");
        }
        __syncthreads();

        const uint32_t st = sb + (i & 1) * STAGE_B;
#pragma unroll
        for (int ks = 0; ks < 4; ks++) {
            const int cb = ks * 32 + ((lane >> 4) << 4);
            uint32_t ah[2][4], al[2][4], wh[2][4], wl[2][4];
#pragma unroll
            for (int mi = 0; mi < 2; mi++) {
                int r = warp_m * 32 + mi * 16 + (lane & 15);
                uint32_t boff = r * 128 + cb;
                uint32_t sw = boff ^ ((boff >> 3) & 0x70);
                ldsm_x4(ah[mi], st + sw);
                ldsm_x4(al[mi], st + TILE_B + sw);
            }
#pragma unroll
            for (int np = 0; np < 2; np++) {
                int r = warp_n * 32 + np * 16 + (lane & 15);
                uint32_t boff = r * 128 + cb;
                uint32_t sw = boff ^ ((boff >> 3) & 0x70);
                ldsm_x4(wh[np], st + 2 * TILE_B + sw);
                ldsm_x4(wl[np], st + 3 * TILE_B + sw);
            }
#pragma unroll
            for (int mi = 0; mi < 2; mi++)
#pragma unroll
                for (int nj = 0; nj < 4; nj++) {
                    int np = nj >> 1, o = nj & 1;
                    mma_bf16(acc[mi][nj], ah[mi], wh[np][o], wh[np][o + 2]);
                    mma_bf16(acc[mi][nj], ah[mi], wl[np][o], wl[np][o + 2]);
                    mma_bf16(acc[mi][nj], al[mi], wh[np][o], wh[np][o + 2]);
                }
        }
        __syncthreads();
    }

    const int r0 = lane >> 2, c0 = (lane & 3) * 2;
#pragma unroll
    for (int mi = 0; mi < 2; mi++) {
#pragma unroll
        for (int nj = 0; nj < 4; nj++) {
            int row = bm + warp_m * 32 + mi * 16 + r0;
            int col = bn + warp_n * 32 + nj * 8 + c0;
            float2 b2 = *(const float2*)&bias[col];
            float v0 = (acc[mi][nj][0] + b2.x) * scale;
            float v1 = (acc[mi][nj][1] + b2.y) * scale;
            float v2 = (acc[mi][nj][2] + b2.x) * scale;
            float v3 = (acc[mi][nj][3] + b2.y) * scale;
            if (Chi) {
                __nv_bfloat162 h0, h1;
                uint32_t u0 = pack_hi(v0, v1, h0), u1 = pack_hi(v2, v3, h1);
                uint32_t l0 = pack_lo(v0, v1, h0), l1 = pack_lo(v2, v3, h1);
                *(uint32_t*)&Chi[(size_t)row * DMODEL + col] = u0;
                *(uint32_t*)&Clo[(size_t)row * DMODEL + col] = l0;
                *(uint32_t*)&Chi[(size_t)(row + 8) * DMODEL + col] = u1;
                *(uint32_t*)&Clo[(size_t)(row + 8) * DMODEL + col] = l1;
            } else {
                *(float2*)&C[(size_t)row * DMODEL + col] = make_float2(v0, v1);
                *(float2*)&C[(size_t)(row + 8) * DMODEL + col] = make_float2(v2, v3);
            }
        }
    }
}

// ---------------- flash attention: Bc=128 (R15 form, unchanged) --------------
#define FA_SUB   49152
#define FA_STAGE (2 * FA_SUB)
#define FA_SMEM  (2 * FA_STAGE)
#define NBLK128  (SLEN / 128)

__global__ __launch_bounds__(256, 1) void flash_attn_mma(
    const __nv_bfloat16* __restrict__ Qhi, const __nv_bfloat16* __restrict__ Qlo,
    const __nv_bfloat16* __restrict__ Khi, const __nv_bfloat16* __restrict__ Klo,
    const __nv_bfloat16* __restrict__ Vhi, const __nv_bfloat16* __restrict__ Vlo,
    const __nv_bfloat16* __restrict__ bias,
    __nv_bfloat16* __restrict__ Ahi, __nv_bfloat16* __restrict__ Alo)
{
    extern __shared__ __align__(1024) char smem[];
    const uint32_t sb = smem_u32(smem);
    const int tid = threadIdx.x, wid = tid >> 5, lane = tid & 31;
    const int q0 = blockIdx.x * 128, h = blockIdx.y, b = blockIdx.z;

    const size_t tok0 = (size_t)b * SLEN;
    const size_t hoff = (size_t)h * DKH;
    const int qr = q0 + wid * 16 + (lane >> 2);

    uint32_t qh[4][4], ql[4][4];
    {
        const size_t b0 = (tok0 + qr) * DMODEL + hoff;
        const size_t b1 = (tok0 + qr + 8) * DMODEL + hoff;
#pragma unroll
        for (int t = 0; t < 4; t++) {
            int c = t * 16 + 2 * (lane & 3);
            qh[t][0] = *(const uint32_t*)&Qhi[b0 + c];
            qh[t][1] = *(const uint32_t*)&Qhi[b1 + c];
            qh[t][2] = *(const uint32_t*)&Qhi[b0 + c + 8];
            qh[t][3] = *(const uint32_t*)&Qhi[b1 + c + 8];
            ql[t][0] = *(const uint32_t*)&Qlo[b0 + c];
            ql[t][1] = *(const uint32_t*)&Qlo[b1 + c];
            ql[t][2] = *(const uint32_t*)&Qlo[b0 + c + 8];
            ql[t][3] = *(const uint32_t*)&Qlo[b1 + c + 8];
        }
    }

    const __nv_bfloat16* srcs[4] = {
        Khi + tok0 * DMODEL + hoff, Klo + tok0 * DMODEL + hoff,
        Vhi + tok0 * DMODEL + hoff, Vlo + tok0 * DMODEL + hoff };
    const __nv_bfloat16* brow = bias + (tok0 + q0) * SLEN;

    auto load_sub = [&](int k0, uint32_t st) {
#pragma unroll
        for (int i = 0; i < 8; i++) {
            int idx = tid + i * 256;
            int a = idx >> 9, r = (idx >> 3) & 63, c8 = idx & 7;
            uint32_t boff = r * 128 + c8 * 16;
            uint32_t sw = boff ^ ((boff >> 3) & 0x70);
            const void* g = srcs[a] + (size_t)(k0 + r) * DMODEL + c8 * 8;
            asm volatile("cp.async.cg.shared.global [%0], [%1], 16;"
                         :: "r"(st + a * 8192 + sw), "l"(g));
        }
#pragma unroll
        for (int i = 0; i < 4; i++) {
            int idx = tid + i * 256;
            int r = idx >> 3, c8 = idx & 7;
            uint32_t boff = r * 128 + c8 * 16;
            uint32_t sw = boff ^ ((boff >> 3) & 0x70);
            const void* g = brow + (size_t)r * SLEN + k0 + c8 * 8;
            asm volatile("cp.async.cg.shared.global [%0], [%1], 16;"
                         :: "r"(st + 32768 + sw), "l"(g));
        }
    };
    auto load_kv128 = [&](int blk, int stage) {
        const uint32_t st = sb + stage * FA_STAGE;
        load_sub(blk * 128, st);
        load_sub(blk * 128 + 64, st + FA_SUB);
        asm volatile("cp.async.commit_group;" ::: "memory");
    };

    float l[2] = { 0.f, 0.f };
    float o[8][4];
#pragma unroll
    for (int j = 0; j < 8; j++)
#pragma unroll
        for (int e = 0; e < 4; e++) o[j][e] = 0.f;

    load_kv128(0, 0);

    for (int blk = 0; blk < NBLK128; blk++) {
        if (blk + 1 < NBLK128) {
            load_kv128(blk + 1, (blk + 1) & 1);
            asm volatile("cp.async.wait_group 1;" ::: "memory");
        } else {
            asm volatile("cp.async.wait_group 0;" ::: "memory");
        }
        __syncthreads();

#pragma unroll
        for (int half = 0; half < 2; half++) {
            const uint32_t st = sb + (blk & 1) * FA_STAGE + half * FA_SUB;

            float S[8][4];
#pragma unroll
            for (int j = 0; j < 8; j++)
#pragma unroll
                for (int e = 0; e < 4; e++) S[j][e] = 0.f;

#pragma unroll
            for (int t = 0; t < 4; t++) {
                const int cb = t * 32 + ((lane >> 4) << 4);
#pragma unroll
                for (int np = 0; np < 4; np++) {
                    int r = np * 16 + (lane & 15);
                    uint32_t boff = r * 128 + cb;
                    uint32_t sw = boff ^ ((boff >> 3) & 0x70);
                    uint32_t kh[4], kl[4];
                    ldsm_x4(kh, st + sw);
                    ldsm_x4(kl, st + 8192 + sw);
#pragma unroll
                    for (int o2 = 0; o2 < 2; o2++) {
                        int j = np * 2 + o2;
                        mma_bf16(S[j], qh[t], kh[o2], kh[o2 + 2]);
                        mma_bf16(S[j], qh[t], kl[o2], kl[o2 + 2]);
                        mma_bf16(S[j], ql[t], kh[o2], kh[o2 + 2]);
                    }
                }
            }

#pragma unroll
            for (int j2 = 0; j2 < 4; j2++) {
                uint32_t bf[4];
                int rr = wid * 16 + ((lane >> 3) & 1) * 8 + (lane & 7);
                int cc = (j2 * 2 + (lane >> 4)) * 16;
                uint32_t boff = rr * 128 + cc;
                uint32_t sw = boff ^ ((boff >> 3) & 0x70);
                ldsm_x4(bf, st + 32768 + sw);
                float2 f;
                f = __bfloat1622float2(*(__nv_bfloat162*)&bf[0]);
                S[2 * j2][0] += f.x; S[2 * j2][1] += f.y;
                f = __bfloat1622float2(*(__nv_bfloat162*)&bf[1]);
                S[2 * j2][2] += f.x; S[2 * j2][3] += f.y;
                f = __bfloat1622float2(*(__nv_bfloat162*)&bf[2]);
                S[2 * j2 + 1][0] += f.x; S[2 * j2 + 1][1] += f.y;
                f = __bfloat1622float2(*(__nv_bfloat162*)&bf[3]);
                S[2 * j2 + 1][2] += f.x; S[2 * j2 + 1][3] += f.y;
            }
#pragma unroll
            for (int j = 0; j < 8; j++) {
                S[j][0] = ex2(S[j][0]); S[j][1] = ex2(S[j][1]);
                S[j][2] = ex2(S[j][2]); S[j][3] = ex2(S[j][3]);
                l[0] += S[j][0] + S[j][1];
                l[1] += S[j][2] + S[j][3];
            }

#pragma unroll
            for (int t = 0; t < 4; t++) {
                uint32_t ph[4], pl[4];
                {
                    __nv_bfloat162 h2;
                    ph[0] = pack_hi(S[2 * t][0], S[2 * t][1], h2);
                    pl[0] = pack_lo(S[2 * t][0], S[2 * t][1], h2);
                    ph[1] = pack_hi(S[2 * t][2], S[2 * t][3], h2);
                    pl[1] = pack_lo(S[2 * t][2], S[2 * t][3], h2);
                    ph[2] = pack_hi(S[2 * t + 1][0], S[2 * t + 1][1], h2);
                    pl[2] = pack_lo(S[2 * t + 1][0], S[2 * t + 1][1], h2);
                    ph[3] = pack_hi(S[2 * t + 1][2], S[2 * t + 1][3], h2);
                    pl[3] = pack_lo(S[2 * t + 1][2], S[2 * t + 1][3], h2);
                }
                const int vkey = t * 16 + ((lane >> 3) & 1) * 8 + (lane & 7);
#pragma unroll
                for (int g = 0; g < 4; g++) {
                    int dcol = g * 16 + ((lane >> 4) & 1) * 8;
                    uint32_t boff = vkey * 128 + dcol * 2;
                    uint32_t sw = boff ^ ((boff >> 3) & 0x70);
                    uint32_t vh[4], vl[4];
                    ldsm_x4_t(vh, st + 16384 + sw);
                    ldsm_x4_t(vl, st + 24576 + sw);
#pragma unroll
                    for (int o2 = 0; o2 < 2; o2++) {
                        int j = g * 2 + o2;
                        mma_bf16(o[j], ph, vh[o2 * 2], vh[o2 * 2 + 1]);
                        mma_bf16(o[j], ph, vl[o2 * 2], vl[o2 * 2 + 1]);
                        mma_bf16(o[j], pl, vh[o2 * 2], vh[o2 * 2 + 1]);
                    }
                }
            }
        }
        __syncthreads();
    }

    l[0] += __shfl_xor_sync(0xffffffffu, l[0], 1);
    l[0] += __shfl_xor_sync(0xffffffffu, l[0], 2);
    l[1] += __shfl_xor_sync(0xffffffffu, l[1], 1);
    l[1] += __shfl_xor_sync(0xffffffffu, l[1], 2);
    const float i0 = 1.f / l[0], i1 = 1.f / l[1];
#pragma unroll
    for (int j = 0; j < 8; j++) {
        int c = j * 8 + 2 * (lane & 3);
        size_t a0 = (tok0 + qr) * DMODEL + hoff + c;
        size_t a1 = (tok0 + qr + 8) * DMODEL + hoff + c;
        __nv_bfloat162 h2;
        float f0 = o[j][0] * i0, f1 = o[j][1] * i0;
        uint32_t u = pack_hi(f0, f1, h2), v = pack_lo(f0, f1, h2);
        *(uint32_t*)&Ahi[a0] = u; *(uint32_t*)&Alo[a0] = v;
        f0 = o[j][2] * i1; f1 = o[j][3] * i1;
        u = pack_hi(f0, f1, h2); v = pack_lo(f0, f1, h2);
        *(uint32_t*)&Ahi[a1] = u; *(uint32_t*)&Alo[a1] = v;
    }
}

// ---------------- launcher ---------------------------------------------------
extern "C" void kernel_launch(void* const* d_in, const int* in_sizes, int n_in,
                              void* d_out, int out_size)
{
    const float* query = (const float*)d_in[0];
    const float* key   = (const float*)d_in[1];
    const float* value = (const float*)d_in[2];
    const int*   mask  = (const int*)d_in[3];
    const float* Wq    = (const float*)d_in[4];
    const float* bq    = (const float*)d_in[5];
    const float* Wk    = (const float*)d_in[6];
    const float* bk    = (const float*)d_in[7];
    const float* Wv    = (const float*)d_in[8];
    const float* bv    = (const float*)d_in[9];
    const float* Wo    = (const float*)d_in[10];
    const float* bo    = (const float*)d_in[11];
    float* out = (float*)d_out;

    __nv_bfloat16 *qhi, *qlo, *khi, *klo, *vhi, *vlo, *ahi, *alo, *bb;
    __nv_bfloat16 *xh[3], *xl[3], *wh[4], *wl[4];
    cudaGetSymbolAddress((void**)&qhi, g_qhi);
    cudaGetSymbolAddress((void**)&qlo, g_qlo);
    cudaGetSymbolAddress((void**)&khi, g_khi);
    cudaGetSymbolAddress((void**)&klo, g_klo);
    cudaGetSymbolAddress((void**)&vhi, g_vhi);
    cudaGetSymbolAddress((void**)&vlo, g_vlo);
    cudaGetSymbolAddress((void**)&ahi, g_ahi);
    cudaGetSymbolAddress((void**)&alo, g_alo);
    cudaGetSymbolAddress((void**)&bb,  g_bias);
    {
        __nv_bfloat16 *p;
        cudaGetSymbolAddress((void**)&p, g_xh);
        for (int i = 0; i < 3; i++) xh[i] = p + (size_t)i * MROWS * DMODEL;
        cudaGetSymbolAddress((void**)&p, g_xl);
        for (int i = 0; i < 3; i++) xl[i] = p + (size_t)i * MROWS * DMODEL;
        cudaGetSymbolAddress((void**)&p, g_wh);
        for (int i = 0; i < 4; i++) wh[i] = p + (size_t)i * DMODEL * DMODEL;
        cudaGetSymbolAddress((void**)&p, g_wl);
        for (int i = 0; i < 4; i++) wl[i] = p + (size_t)i * DMODEL * DMODEL;
    }

    cudaFuncSetAttribute(gemm_mma, cudaFuncAttributeMaxDynamicSharedMemorySize, GEMM_SMEM);
    cudaFuncSetAttribute(flash_attn_mma, cudaFuncAttributeMaxDynamicSharedMemorySize, FA_SMEM);

    {
        PrepArgs p{};
        p.xin[0] = (const float4*)query;
        p.xin[1] = (const float4*)key;
        p.xin[2] = (const float4*)value;
        for (int i = 0; i < 3; i++) {
            p.xhi[i] = (__nv_bfloat162*)xh[i];
            p.xlo[i] = (__nv_bfloat162*)xl[i];
        }
        const float* Ws[4] = { Wq, Wk, Wv, Wo };
        for (int i = 0; i < 4; i++) {
            p.win[i] = (const float4*)Ws[i];
            p.whi[i] = (__nv_bfloat162*)wh[i];
            p.wlo[i] = (__nv_bfloat162*)wl[i];
        }
        p.mk = (const int4*)mask;
        p.bias = (__nv_bfloat162*)bb;
        prep_all<<<(PREP_UNITS + 255) / 256, 256>>>(p);
    }

    const float QSCALE = 0.125f * 1.4426950408889634f;

    // batched QKV projection GEMM (grid.z = 3; measured faster than sequential)
    {
        GemmJobs jb{};
        const float* bs[3] = { bq, bk, bv };
        __nv_bfloat16* chs[3] = { qhi, khi, vhi };
        __nv_bfloat16* cls[3] = { qlo, klo, vlo };
        float sc[3] = { QSCALE, 1.f, 1.f };
        for (int i = 0; i < 3; i++) {
            jb.xhi[i] = xh[i]; jb.xlo[i] = xl[i];
            jb.whi[i] = wh[i]; jb.wlo[i] = wl[i];
            jb.bias[i] = bs[i]; jb.C[i] = nullptr;
            jb.Chi[i] = chs[i]; jb.Clo[i] = cls[i];
            jb.scale[i] = sc[i];
        }
        gemm_mma<<<dim3(DMODEL / 128, MROWS / 128, 3), 512, GEMM_SMEM>>>(jb);
    }

    dim3 fg(SLEN / 128, NHEAD, BATCH);
    flash_attn_mma<<<fg, 256, FA_SMEM>>>(qhi, qlo, khi, klo, vhi, vlo, bb, ahi, alo);

    // output projection (depends on attention)
    {
        GemmJobs jb{};
        jb.xhi[0] = ahi; jb.xlo[0] = alo;
        jb.whi[0] = wh[3]; jb.wlo[0] = wl[3];
        jb.bias[0] = bo; jb.C[0] = out;
        jb.Chi[0] = nullptr; jb.Clo[0] = nullptr;
        jb.scale[0] = 1.f;
        gemm_mma<<<dim3(DMODEL / 128, MROWS / 128, 1), 512, GEMM_SMEM>>>(jb);
    }
}